// round 12
// baseline (speedup 1.0000x reference)
#include <cuda_runtime.h>
#include <cuda_bf16.h>
#include <cstdint>

#define D_MODEL 1024
#define HEADS   16
#define DK      64
#define SEQ     2048
#define BATCH   4
#define BH      (BATCH*HEADS)
#define MTOT    (BATCH*SEQ)          // 8192

// ---------------- scratch (device globals: allocation-free) ----------------
__device__ __nv_bfloat16 g_xhi[MTOT*D_MODEL];
__device__ __nv_bfloat16 g_xlo[MTOT*D_MODEL];
__device__ __nv_bfloat16 g_whi[4][D_MODEL*D_MODEL];
__device__ __nv_bfloat16 g_wlo[4][D_MODEL*D_MODEL];
__device__ __nv_bfloat16 g_qhi[BH*SEQ*DK];
__device__ __nv_bfloat16 g_qlo[BH*SEQ*DK];
__device__ __nv_bfloat16 g_khi[BH*SEQ*DK];
__device__ __nv_bfloat16 g_klo[BH*SEQ*DK];
__device__ __nv_bfloat16 g_vhi[BH*DK*SEQ];   // transposed [bh][d][s]
__device__ __nv_bfloat16 g_vlo[BH*DK*SEQ];
__device__ __nv_bfloat16 g_ahi[MTOT*D_MODEL];
__device__ __nv_bfloat16 g_alo[MTOT*D_MODEL];

// ---------------- helpers ----------------
__device__ __forceinline__ uint32_t smem_u32(const void* p) {
    uint32_t a;
    asm("{ .reg .u64 t; cvta.to.shared.u64 t, %1; cvt.u32.u64 %0, t; }"
        : "=r"(a) : "l"(p));
    return a;
}
__device__ __forceinline__ void cp16(uint32_t saddr, const void* gaddr) {
    asm volatile("cp.async.cg.shared.global [%0], [%1], 16;"
                 :: "r"(saddr), "l"(gaddr));
}
__device__ __forceinline__ void cp_commit() {
    asm volatile("cp.async.commit_group;");
}
__device__ __forceinline__ void ldmatrix4(uint32_t& r0, uint32_t& r1,
                                          uint32_t& r2, uint32_t& r3, uint32_t addr) {
    asm volatile("ldmatrix.sync.aligned.m8n8.x4.shared.b16 {%0,%1,%2,%3}, [%4];"
                 : "=r"(r0), "=r"(r1), "=r"(r2), "=r"(r3) : "r"(addr));
}
__device__ __forceinline__ void mma_bf16(float* c, const uint32_t* a, const uint32_t* b) {
    asm volatile("mma.sync.aligned.m16n8k16.row.col.f32.bf16.bf16.f32 "
                 "{%0,%1,%2,%3}, {%4,%5,%6,%7}, {%8,%9}, {%0,%1,%2,%3};"
                 : "+f"(c[0]), "+f"(c[1]), "+f"(c[2]), "+f"(c[3])
                 : "r"(a[0]), "r"(a[1]), "r"(a[2]), "r"(a[3]),
                   "r"(b[0]), "r"(b[1]));
}
__device__ __forceinline__ uint32_t pack_hi(float a, float b, float& ra, float& rb) {
    __nv_bfloat16 h0 = __float2bfloat16(a);
    __nv_bfloat16 h1 = __float2bfloat16(b);
    ra = a - __bfloat162float(h0);
    rb = b - __bfloat162float(h1);
    __nv_bfloat162 t = __halves2bfloat162(h0, h1);
    return *(uint32_t*)&t;
}
__device__ __forceinline__ uint32_t pack_bf(float a, float b) {
    __nv_bfloat162 t = __halves2bfloat162(__float2bfloat16(a), __float2bfloat16(b));
    return *(uint32_t*)&t;
}
__device__ __forceinline__ void store_hl(__nv_bfloat16* hi, __nv_bfloat16* lo,
                                         size_t idx, float v0, float v1) {
    __nv_bfloat16 h0 = __float2bfloat16(v0);
    __nv_bfloat16 h1 = __float2bfloat16(v1);
    *(__nv_bfloat162*)(hi + idx) = __halves2bfloat162(h0, h1);
    *(__nv_bfloat162*)(lo + idx) = __halves2bfloat162(
        __float2bfloat16(v0 - __bfloat162float(h0)),
        __float2bfloat16(v1 - __bfloat162float(h1)));
}

// ---------------- split fp32 -> (hi, lo) bf16 ----------------
__global__ void split_kernel(const float* __restrict__ in,
                             __nv_bfloat16* __restrict__ hi,
                             __nv_bfloat16* __restrict__ lo, int n4)
{
    int i = blockIdx.x * blockDim.x + threadIdx.x;
    if (i >= n4) return;
    float4 v = ((const float4*)in)[i];
    float r0, r1, r2, r3;
    uint32_t h01 = pack_hi(v.x, v.y, r0, r1);
    uint32_t h23 = pack_hi(v.z, v.w, r2, r3);
    ((uint32_t*)hi)[2*i+0] = h01;
    ((uint32_t*)hi)[2*i+1] = h23;
    ((uint32_t*)lo)[2*i+0] = pack_bf(r0, r1);
    ((uint32_t*)lo)[2*i+1] = pack_bf(r2, r3);
}

// fused weight split: z selects the weight matrix
__global__ void split_w_kernel(const float* __restrict__ W0,
                               const float* __restrict__ W1,
                               const float* __restrict__ W2,
                               const float* __restrict__ W3,
                               __nv_bfloat16* __restrict__ hi,
                               __nv_bfloat16* __restrict__ lo, int n4)
{
    const int z = blockIdx.z;
    const float* in = (z == 0) ? W0 : (z == 1) ? W1 : (z == 2) ? W2 : W3;
    hi += (size_t)z * D_MODEL * D_MODEL;
    lo += (size_t)z * D_MODEL * D_MODEL;
    int i = blockIdx.x * blockDim.x + threadIdx.x;
    if (i >= n4) return;
    float4 v = ((const float4*)in)[i];
    float r0, r1, r2, r3;
    uint32_t h01 = pack_hi(v.x, v.y, r0, r1);
    uint32_t h23 = pack_hi(v.z, v.w, r2, r3);
    ((uint32_t*)hi)[2*i+0] = h01;
    ((uint32_t*)hi)[2*i+1] = h23;
    ((uint32_t*)lo)[2*i+0] = pack_bf(r0, r1);
    ((uint32_t*)lo)[2*i+1] = pack_bf(r2, r3);
}

// ---- mma.sync split-bf16 GEMM: 128x128, 256 thr, 8 warps 2mx4n, warp 64x32,
//      BK=32, 2-stage depth-1 prefetch, 2 CTAs/SM --------------------------
#define BM 128
#define BN 128
#define BK 32
#define SROWB 80                      // 64 B data + 16 pad
#define TILE_B (128 * SROWB)          // 10240
#define AHI_OFF  0
#define ALO_OFF  (TILE_B)
#define BHI_OFF  (2*TILE_B)
#define BLO_OFF  (3*TILE_B)
#define STAGE_B  (4*TILE_B)           // 40960
#define GEMM_SMEM (2*STAGE_B)         // 81920 -> 2 CTAs/SM
#define GTHREADS 256
#define WSZ ((size_t)D_MODEL*D_MODEL)

__global__ __launch_bounds__(GTHREADS, 2)
void gemm_mma_kernel(const __nv_bfloat16* __restrict__ Ahi,
                     const __nv_bfloat16* __restrict__ Alo,
                     const __nv_bfloat16* __restrict__ Wh,
                     const __nv_bfloat16* __restrict__ Wl,
                     float* __restrict__ Cf,
                     __nv_bfloat16* __restrict__ Qhi, __nv_bfloat16* __restrict__ Qlo,
                     __nv_bfloat16* __restrict__ Khi, __nv_bfloat16* __restrict__ Klo,
                     __nv_bfloat16* __restrict__ Vhi, __nv_bfloat16* __restrict__ Vlo,
                     int qkv)
{
    extern __shared__ char smem[];
    const uint32_t sbase = smem_u32(smem);
    const int tid = threadIdx.x;
    const int wid = tid >> 5;
    const int lane = tid & 31;
    const int wm = wid & 1;           // 2 m groups of 64
    const int wn = wid >> 1;          // 4 n groups of 32

    const int z = qkv ? blockIdx.z : 0;
    const int m0 = blockIdx.y * BM;
    const int n0 = blockIdx.x * BN;

    const __nv_bfloat16* Ah = Ahi + (size_t)m0 * 1024;
    const __nv_bfloat16* Al = Alo + (size_t)m0 * 1024;
    const __nv_bfloat16* Bh = Wh + (qkv ? (size_t)z * WSZ : 0) + (size_t)n0 * 1024;
    const __nv_bfloat16* Bl = Wl + (qkv ? (size_t)z * WSZ : 0) + (size_t)n0 * 1024;
    const __nv_bfloat16* srcs[4] = {Ah, Al, Bh, Bl};

    auto load_stage = [&](int ch, int st) {
        const int k0 = ch * BK;
        const uint32_t sb = sbase + st * STAGE_B;
#pragma unroll
        for (int i = 0; i < 8; i++) {
            const int idx = tid + i * GTHREADS;   // 0..2047
            const int t4 = idx >> 9;              // tile 0..3 (512 xfers each)
            const int r = (idx >> 2) & 127;
            const int c = idx & 3;                // 4 x 16B = 64 B per row
            cp16(sb + t4 * TILE_B + (uint32_t)(r * SROWB + c * 16),
                 srcs[t4] + (size_t)r * 1024 + k0 + c * 8);
        }
        cp_commit();
    };

    float acc[4][4][4];
#pragma unroll
    for (int i = 0; i < 4; i++)
#pragma unroll
        for (int j = 0; j < 4; j++)
#pragma unroll
            for (int t = 0; t < 4; t++) acc[i][j][t] = 0.f;

    const int NCH = 1024 / BK;        // 32
    load_stage(0, 0);

    for (int ch = 0; ch < NCH; ch++) {
        asm volatile("cp.async.wait_group 0;");
        __syncthreads();              // chunk ch visible; other stage free
        if (ch + 1 < NCH) load_stage(ch + 1, (ch + 1) & 1);

        const uint32_t sb = sbase + (ch & 1) * STAGE_B;
#pragma unroll
        for (int ks = 0; ks < 2; ks++) {
            const int k16 = ks * 16;
            // B fragments resident for this k16 (4 n8 frags, hi+lo)
            uint32_t bhi[4][2], blo[4][2];
#pragma unroll
            for (int nf16 = 0; nf16 < 2; nf16++) {
                const int nrow = wn * 32 + nf16 * 16 + ((lane >> 4) << 3) + (lane & 7);
                const int kc   = k16 + (((lane >> 3) & 1) << 3);
                const uint32_t off = (uint32_t)(nrow * SROWB + kc * 2);
                ldmatrix4(bhi[nf16*2][0], bhi[nf16*2][1],
                          bhi[nf16*2+1][0], bhi[nf16*2+1][1], sb + BHI_OFF + off);
                ldmatrix4(blo[nf16*2][0], blo[nf16*2][1],
                          blo[nf16*2+1][0], blo[nf16*2+1][1], sb + BLO_OFF + off);
            }
            // A fragments transient per mf (register liveness control)
#pragma unroll
            for (int mf = 0; mf < 4; mf++) {
                uint32_t ahi[4], alo[4];
                const int row = wm * 64 + mf * 16 + (lane & 15);
                const int kc  = k16 + ((lane >> 4) << 3);
                const uint32_t off = (uint32_t)(row * SROWB + kc * 2);
                ldmatrix4(ahi[0], ahi[1], ahi[2], ahi[3], sb + AHI_OFF + off);
                ldmatrix4(alo[0], alo[1], alo[2], alo[3], sb + ALO_OFF + off);
#pragma unroll
                for (int nf = 0; nf < 4; nf++) {
                    mma_bf16(acc[mf][nf], ahi, bhi[nf]);
                    mma_bf16(acc[mf][nf], ahi, blo[nf]);
                    mma_bf16(acc[mf][nf], alo, bhi[nf]);
                }
            }
        }
    }

    // ---- epilogue ----
    const float scale = qkv ? (z == 0 ? 0.125f : 1.0f) : 1.0f;
    const int mode = qkv ? (z == 2 ? 2 : 1) : 0;
    __nv_bfloat16* Chi = (z == 0) ? Qhi : (z == 1) ? Khi : Vhi;
    __nv_bfloat16* Clo = (z == 0) ? Qlo : (z == 1) ? Klo : Vlo;

#pragma unroll
    for (int mf = 0; mf < 4; mf++) {
#pragma unroll
        for (int nf = 0; nf < 4; nf++) {
            const int m_base = m0 + wm * 64 + mf * 16;
            const int n = n0 + wn * 32 + nf * 8 + (lane & 3) * 2;
            const int r0 = m_base + (lane >> 2);
            const int r1 = r0 + 8;
            const float v0 = acc[mf][nf][0] * scale;
            const float v1 = acc[mf][nf][1] * scale;
            const float v2 = acc[mf][nf][2] * scale;
            const float v3 = acc[mf][nf][3] * scale;
            if (mode == 0) {
                *(float2*)(Cf + (size_t)r0 * 1024 + n) = make_float2(v0, v1);
                *(float2*)(Cf + (size_t)r1 * 1024 + n) = make_float2(v2, v3);
            } else if (mode == 1) {
                const int h = n >> 6, d = n & 63;
                const int bh0 = ((r0 >> 11) * HEADS) + h;
                const int bh1 = ((r1 >> 11) * HEADS) + h;
                store_hl(Chi, Clo, ((size_t)bh0 * SEQ + (r0 & 2047)) * DK + d, v0, v1);
                store_hl(Chi, Clo, ((size_t)bh1 * SEQ + (r1 & 2047)) * DK + d, v2, v3);
            } else {
                const int h = n >> 6, d = n & 63;
                const int bh0 = ((r0 >> 11) * HEADS) + h;
                const int bh1 = ((r1 >> 11) * HEADS) + h;
                const int s0 = r0 & 2047, s1 = r1 & 2047;
                {
                    size_t e = ((size_t)bh0 * DK + d) * SEQ + s0;
                    __nv_bfloat16 h0 = __float2bfloat16(v0);
                    Chi[e] = h0; Clo[e] = __float2bfloat16(v0 - __bfloat162float(h0));
                    e += SEQ;
                    __nv_bfloat16 h1 = __float2bfloat16(v1);
                    Chi[e] = h1; Clo[e] = __float2bfloat16(v1 - __bfloat162float(h1));
                }
                {
                    size_t e = ((size_t)bh1 * DK + d) * SEQ + s1;
                    __nv_bfloat16 h2 = __float2bfloat16(v2);
                    Chi[e] = h2; Clo[e] = __float2bfloat16(v2 - __bfloat162float(h2));
                    e += SEQ;
                    __nv_bfloat16 h3 = __float2bfloat16(v3);
                    Chi[e] = h3; Clo[e] = __float2bfloat16(v3 - __bfloat162float(h3));
                }
            }
        }
    }
}

// ---------------- mma.sync flash attention (causal, split-bf16) -------------
// 2 CTAs/SM (launch_bounds cap 128 regs); Q frags re-read from smem per block.
#define ASTR 144
#define AQHI 0
#define AQLO 18432
#define ASTG0 36864
#define AKHI 0
#define AKLO 9216
#define AVHI 18432
#define AVLO 27648
#define ASTAGE_B 36864
#define ATT_SMEM (36864 + 2*36864)    // 110592

__global__ __launch_bounds__(256, 2)
void attn_mma_kernel(const __nv_bfloat16* __restrict__ Qhi,
                     const __nv_bfloat16* __restrict__ Qlo,
                     const __nv_bfloat16* __restrict__ Khi,
                     const __nv_bfloat16* __restrict__ Klo,
                     const __nv_bfloat16* __restrict__ Vhi,
                     const __nv_bfloat16* __restrict__ Vlo,
                     __nv_bfloat16* __restrict__ Ohi,
                     __nv_bfloat16* __restrict__ Olo)
{
    extern __shared__ char smem[];
    const uint32_t sbase = smem_u32(smem);
    const int tid = threadIdx.x;
    const int w = tid >> 5;
    const int lane = tid & 31;
    const int qt = (int)gridDim.x - 1 - (int)blockIdx.x;  // big tiles first
    const int bh = blockIdx.y;

    const __nv_bfloat16* Qh = Qhi + (size_t)bh * SEQ * DK + (size_t)qt * 128 * DK;
    const __nv_bfloat16* Ql = Qlo + (size_t)bh * SEQ * DK + (size_t)qt * 128 * DK;
    const __nv_bfloat16* Kh = Khi + (size_t)bh * SEQ * DK;
    const __nv_bfloat16* Kl = Klo + (size_t)bh * SEQ * DK;
    const __nv_bfloat16* Vh = Vhi + (size_t)bh * DK * SEQ;
    const __nv_bfloat16* Vl = Vlo + (size_t)bh * DK * SEQ;

    {
#pragma unroll
        for (int i = 0; i < 4; i++) {
            const int idx = tid + i * 256;
            const int row = idx >> 3, c = idx & 7;
            const uint32_t so = (uint32_t)(row * ASTR + c * 16);
            const size_t go = (size_t)row * DK + c * 8;
            cp16(sbase + AQHI + so, Qh + go);
            cp16(sbase + AQLO + so, Ql + go);
        }
        cp_commit();
    }

    const int jmax = 2 * qt + 1;
    auto load_kv = [&](int j, int st) {
        const uint32_t sb = sbase + ASTG0 + st * ASTAGE_B;
#pragma unroll
        for (int i = 0; i < 2; i++) {
            const int idx = tid + i * 256;
            const int row = idx >> 3, c = idx & 7;
            const uint32_t so = (uint32_t)(row * ASTR + c * 16);
            const size_t gk = (size_t)(j * 64 + row) * DK + c * 8;
            const size_t gv = (size_t)row * SEQ + j * 64 + c * 8;
            cp16(sb + AKHI + so, Kh + gk);
            cp16(sb + AKLO + so, Kl + gk);
            cp16(sb + AVHI + so, Vh + gv);
            cp16(sb + AVLO + so, Vl + gv);
        }
        cp_commit();
    };

    load_kv(0, 0);
    asm volatile("cp.async.wait_group 1;");
    __syncthreads();

    float o[8][4];
#pragma unroll
    for (int nf = 0; nf < 8; nf++)
#pragma unroll
        for (int t = 0; t < 4; t++) o[nf][t] = 0.f;
    float mA = -1e30f, mB = -1e30f, lA = 0.f, lB = 0.f;

    const int rowA_g = qt * 128 + w * 16 + (lane >> 2);
    const int rowB_g = rowA_g + 8;

    for (int j = 0; j <= jmax; j++) {
        if (j < jmax) load_kv(j + 1, (j + 1) & 1);
        if (j < jmax) asm volatile("cp.async.wait_group 1;");
        else          asm volatile("cp.async.wait_group 0;");
        __syncthreads();

        const uint32_t sb = sbase + ASTG0 + (j & 1) * ASTAGE_B;

        float s[8][4];
#pragma unroll
        for (int nf = 0; nf < 8; nf++)
#pragma unroll
            for (int t = 0; t < 4; t++) s[nf][t] = 0.f;
#pragma unroll
        for (int kb = 0; kb < 4; kb++) {
            uint32_t qh[4], ql[4];
            {
                const int row = w * 16 + (lane & 15);
                const int kc = kb * 16 + ((lane >> 4) << 3);
                const uint32_t off = (uint32_t)(row * ASTR + kc * 2);
                ldmatrix4(qh[0], qh[1], qh[2], qh[3], sbase + AQHI + off);
                ldmatrix4(ql[0], ql[1], ql[2], ql[3], sbase + AQLO + off);
            }
            uint32_t kh[8][2], kl[8][2];
            const uint32_t kcoff = (uint32_t)((kb * 16 + (((lane >> 3) & 1) << 3)) * 2);
            const int nr = ((lane >> 4) << 3) + (lane & 7);
#pragma unroll
            for (int ng = 0; ng < 4; ng++) {
                const uint32_t off = (uint32_t)((ng * 16 + nr) * ASTR) + kcoff;
                ldmatrix4(kh[2*ng][0], kh[2*ng][1], kh[2*ng+1][0], kh[2*ng+1][1],
                          sb + AKHI + off);
                ldmatrix4(kl[2*ng][0], kl[2*ng][1], kl[2*ng+1][0], kl[2*ng+1][1],
                          sb + AKLO + off);
            }
#pragma unroll
            for (int nf = 0; nf < 8; nf++) {
                mma_bf16(s[nf], qh, kh[nf]);
                mma_bf16(s[nf], qh, kl[nf]);
                mma_bf16(s[nf], ql, kh[nf]);
            }
        }

        if (j >= 2 * qt) {
#pragma unroll
            for (int nf = 0; nf < 8; nf++) {
                const int c0 = j * 64 + nf * 8 + (lane & 3) * 2;
                if (c0 > rowA_g)     s[nf][0] = -1e30f;
                if (c0 + 1 > rowA_g) s[nf][1] = -1e30f;
                if (c0 > rowB_g)     s[nf][2] = -1e30f;
                if (c0 + 1 > rowB_g) s[nf][3] = -1e30f;
            }
        }

        float bmA = -1e30f, bmB = -1e30f;
#pragma unroll
        for (int nf = 0; nf < 8; nf++) {
            bmA = fmaxf(bmA, fmaxf(s[nf][0], s[nf][1]));
            bmB = fmaxf(bmB, fmaxf(s[nf][2], s[nf][3]));
        }
        bmA = fmaxf(bmA, __shfl_xor_sync(0xffffffffu, bmA, 1));
        bmA = fmaxf(bmA, __shfl_xor_sync(0xffffffffu, bmA, 2));
        bmB = fmaxf(bmB, __shfl_xor_sync(0xffffffffu, bmB, 1));
        bmB = fmaxf(bmB, __shfl_xor_sync(0xffffffffu, bmB, 2));
        const float mnA = fmaxf(mA, bmA);
        const float mnB = fmaxf(mB, bmB);
        const float alA = __expf(mA - mnA);
        const float alB = __expf(mB - mnB);
        mA = mnA; mB = mnB;

        float sumA = 0.f, sumB = 0.f;
#pragma unroll
        for (int nf = 0; nf < 8; nf++) {
            s[nf][0] = __expf(s[nf][0] - mnA);
            s[nf][1] = __expf(s[nf][1] - mnA);
            s[nf][2] = __expf(s[nf][2] - mnB);
            s[nf][3] = __expf(s[nf][3] - mnB);
            sumA += s[nf][0] + s[nf][1];
            sumB += s[nf][2] + s[nf][3];
        }
        sumA += __shfl_xor_sync(0xffffffffu, sumA, 1);
        sumA += __shfl_xor_sync(0xffffffffu, sumA, 2);
        sumB += __shfl_xor_sync(0xffffffffu, sumB, 1);
        sumB += __shfl_xor_sync(0xffffffffu, sumB, 2);
        lA = lA * alA + sumA;
        lB = lB * alB + sumB;

#pragma unroll
        for (int nf = 0; nf < 8; nf++) {
            o[nf][0] *= alA; o[nf][1] *= alA;
            o[nf][2] *= alB; o[nf][3] *= alB;
        }

        uint32_t pf_hi[4][4], pf_lo[4][4];
#pragma unroll
        for (int t = 0; t < 4; t++) {
            float r0, r1;
            pf_hi[t][0] = pack_hi(s[2*t][0],   s[2*t][1],   r0, r1); pf_lo[t][0] = pack_bf(r0, r1);
            pf_hi[t][1] = pack_hi(s[2*t][2],   s[2*t][3],   r0, r1); pf_lo[t][1] = pack_bf(r0, r1);
            pf_hi[t][2] = pack_hi(s[2*t+1][0], s[2*t+1][1], r0, r1); pf_lo[t][2] = pack_bf(r0, r1);
            pf_hi[t][3] = pack_hi(s[2*t+1][2], s[2*t+1][3], r0, r1); pf_lo[t][3] = pack_bf(r0, r1);
        }

#pragma unroll
        for (int t = 0; t < 4; t++) {
            uint32_t vh[8][2], vl[8][2];
            const uint32_t kcoff = (uint32_t)((t * 16 + (((lane >> 3) & 1) << 3)) * 2);
            const int nr = ((lane >> 4) << 3) + (lane & 7);
#pragma unroll
            for (int ng = 0; ng < 4; ng++) {
                const uint32_t off = (uint32_t)((ng * 16 + nr) * ASTR) + kcoff;
                ldmatrix4(vh[2*ng][0], vh[2*ng][1], vh[2*ng+1][0], vh[2*ng+1][1],
                          sb + AVHI + off);
                ldmatrix4(vl[2*ng][0], vl[2*ng][1], vl[2*ng+1][0], vl[2*ng+1][1],
                          sb + AVLO + off);
            }
#pragma unroll
            for (int nf = 0; nf < 8; nf++) {
                mma_bf16(o[nf], pf_hi[t], vh[nf]);
                mma_bf16(o[nf], pf_hi[t], vl[nf]);
                mma_bf16(o[nf], pf_lo[t], vh[nf]);
            }
        }
        __syncthreads();
    }

    const float invA = 1.f / lA;
    const float invB = 1.f / lB;
    const int b = bh >> 4, h = bh & 15;
    const size_t mAi = (size_t)(b * SEQ) + (size_t)(rowA_g & 2047);
    const size_t mBi = mAi + 8;
#pragma unroll
    for (int nf = 0; nf < 8; nf++) {
        const int col = h * 64 + nf * 8 + (lane & 3) * 2;
        store_hl(Ohi, Olo, mAi * D_MODEL + col, o[nf][0] * invA, o[nf][1] * invA);
        store_hl(Ohi, Olo, mBi * D_MODEL + col, o[nf][2] * invB, o[nf][3] * invB);
    }
}

// ---------------------------------------------------------------------------
extern "C" void kernel_launch(void* const* d_in, const int* in_sizes, int n_in,
                              void* d_out, int out_size)
{
    (void)in_sizes; (void)n_in; (void)out_size;
    const float* x  = (const float*)d_in[0];
    const float* Wq = (const float*)d_in[1];
    const float* Wk = (const float*)d_in[2];
    const float* Wv = (const float*)d_in[3];
    const float* Wo = (const float*)d_in[4];
    float* out = (float*)d_out;

    __nv_bfloat16 *xhi, *xlo, *whi, *wlo;
    __nv_bfloat16 *qhi, *qlo, *khi, *klo, *vhi, *vlo, *ahi, *alo;
    cudaGetSymbolAddress((void**)&xhi, g_xhi);
    cudaGetSymbolAddress((void**)&xlo, g_xlo);
    cudaGetSymbolAddress((void**)&whi, g_whi);
    cudaGetSymbolAddress((void**)&wlo, g_wlo);
    cudaGetSymbolAddress((void**)&qhi, g_qhi);
    cudaGetSymbolAddress((void**)&qlo, g_qlo);
    cudaGetSymbolAddress((void**)&khi, g_khi);
    cudaGetSymbolAddress((void**)&klo, g_klo);
    cudaGetSymbolAddress((void**)&vhi, g_vhi);
    cudaGetSymbolAddress((void**)&vlo, g_vlo);
    cudaGetSymbolAddress((void**)&ahi, g_ahi);
    cudaGetSymbolAddress((void**)&alo, g_alo);

    cudaFuncSetAttribute(gemm_mma_kernel,
                         cudaFuncAttributeMaxDynamicSharedMemorySize, GEMM_SMEM);
    cudaFuncSetAttribute(attn_mma_kernel,
                         cudaFuncAttributeMaxDynamicSharedMemorySize, ATT_SMEM);

    const int WN4 = D_MODEL * D_MODEL / 4;
    const int XN4 = MTOT * D_MODEL / 4;

    split_kernel<<<XN4 / 256, 256>>>(x, xhi, xlo, XN4);
    split_w_kernel<<<dim3(WN4 / 256, 1, 4), 256>>>(Wq, Wk, Wv, Wo, whi, wlo, WN4);

    // fused Q/K/V projections (blockIdx.z selects weight & output)
    dim3 gq(D_MODEL / BN, MTOT / BM, 3);     // (8, 64, 3)
    gemm_mma_kernel<<<gq, GTHREADS, GEMM_SMEM>>>(xhi, xlo, whi, wlo,
                                            nullptr, qhi, qlo, khi, klo, vhi, vlo, 1);

    attn_mma_kernel<<<dim3(SEQ / 128, BH), 256, ATT_SMEM>>>(qhi, qlo, khi, klo,
                                                            vhi, vlo, ahi, alo);

    // output projection
    dim3 go(D_MODEL / BN, MTOT / BM, 1);     // (8, 64)
    gemm_mma_kernel<<<go, GTHREADS, GEMM_SMEM>>>(ahi, alo, whi + 3*WSZ, wlo + 3*WSZ,
                                            out, qhi, qlo, khi, klo, vhi, vlo, 0);
}

// round 13
// speedup vs baseline: 1.4224x; 1.4224x over previous
#include <cuda_runtime.h>
#include <cuda_fp16.h>
#include <cstdint>

#define D_MODEL 1024
#define HEADS   16
#define DK      64
#define SEQ     2048
#define BATCH   4
#define BH      (BATCH*HEADS)
#define MTOT    (BATCH*SEQ)          // 8192

// ---------------- scratch (device globals: allocation-free) ----------------
__device__ __half g_xhi[MTOT*D_MODEL];
__device__ __half g_xlo[MTOT*D_MODEL];
__device__ __half g_whi[4][D_MODEL*D_MODEL];
__device__ __half g_qhi[BH*SEQ*DK];
__device__ __half g_qlo[BH*SEQ*DK];
__device__ __half g_khi[BH*SEQ*DK];
__device__ __half g_vhi[BH*DK*SEQ];   // transposed [bh][d][s]
__device__ __half g_ahi[MTOT*D_MODEL];
__device__ __half g_alo[MTOT*D_MODEL];

// ---------------- helpers ----------------
__device__ __forceinline__ uint32_t smem_u32(const void* p) {
    uint32_t a;
    asm("{ .reg .u64 t; cvta.to.shared.u64 t, %1; cvt.u32.u64 %0, t; }"
        : "=r"(a) : "l"(p));
    return a;
}
__device__ __forceinline__ void cp16(uint32_t saddr, const void* gaddr) {
    asm volatile("cp.async.cg.shared.global [%0], [%1], 16;"
                 :: "r"(saddr), "l"(gaddr));
}
__device__ __forceinline__ void cp_commit() {
    asm volatile("cp.async.commit_group;");
}
__device__ __forceinline__ void ldmatrix4(uint32_t& r0, uint32_t& r1,
                                          uint32_t& r2, uint32_t& r3, uint32_t addr) {
    asm volatile("ldmatrix.sync.aligned.m8n8.x4.shared.b16 {%0,%1,%2,%3}, [%4];"
                 : "=r"(r0), "=r"(r1), "=r"(r2), "=r"(r3) : "r"(addr));
}
__device__ __forceinline__ void mma_f16(float* c, const uint32_t* a, const uint32_t* b) {
    asm volatile("mma.sync.aligned.m16n8k16.row.col.f32.f16.f16.f32 "
                 "{%0,%1,%2,%3}, {%4,%5,%6,%7}, {%8,%9}, {%0,%1,%2,%3};"
                 : "+f"(c[0]), "+f"(c[1]), "+f"(c[2]), "+f"(c[3])
                 : "r"(a[0]), "r"(a[1]), "r"(a[2]), "r"(a[3]),
                   "r"(b[0]), "r"(b[1]));
}
__device__ __forceinline__ uint32_t pack_hi_h(float a, float b, float& ra, float& rb) {
    __half h0 = __float2half(a);
    __half h1 = __float2half(b);
    ra = a - __half2float(h0);
    rb = b - __half2float(h1);
    __half2 t = __halves2half2(h0, h1);
    return *(uint32_t*)&t;
}
__device__ __forceinline__ uint32_t pack_h(float a, float b) {
    __half2 t = __halves2half2(__float2half(a), __float2half(b));
    return *(uint32_t*)&t;
}
__device__ __forceinline__ void store_hl(__half* hi, __half* lo,
                                         size_t idx, float v0, float v1) {
    __half h0 = __float2half(v0);
    __half h1 = __float2half(v1);
    *(__half2*)(hi + idx) = __halves2half2(h0, h1);
    *(__half2*)(lo + idx) = __halves2half2(
        __float2half(v0 - __half2float(h0)),
        __float2half(v1 - __half2float(h1)));
}

// ---------------- split fp32 -> (hi, lo) fp16 ----------------
__global__ void split_kernel(const float* __restrict__ in,
                             __half* __restrict__ hi,
                             __half* __restrict__ lo, int n4)
{
    int i = blockIdx.x * blockDim.x + threadIdx.x;
    if (i >= n4) return;
    float4 v = ((const float4*)in)[i];
    float r0, r1, r2, r3;
    uint32_t h01 = pack_hi_h(v.x, v.y, r0, r1);
    uint32_t h23 = pack_hi_h(v.z, v.w, r2, r3);
    ((uint32_t*)hi)[2*i+0] = h01;
    ((uint32_t*)hi)[2*i+1] = h23;
    ((uint32_t*)lo)[2*i+0] = pack_h(r0, r1);
    ((uint32_t*)lo)[2*i+1] = pack_h(r2, r3);
}

// fused weight convert: hi only (B-side correction is dropped)
__global__ void conv_w_kernel(const float* __restrict__ W0,
                              const float* __restrict__ W1,
                              const float* __restrict__ W2,
                              const float* __restrict__ W3,
                              __half* __restrict__ hi, int n4)
{
    const int z = blockIdx.z;
    const float* in = (z == 0) ? W0 : (z == 1) ? W1 : (z == 2) ? W2 : W3;
    hi += (size_t)z * D_MODEL * D_MODEL;
    int i = blockIdx.x * blockDim.x + threadIdx.x;
    if (i >= n4) return;
    float4 v = ((const float4*)in)[i];
    ((uint32_t*)hi)[2*i+0] = pack_h(v.x, v.y);
    ((uint32_t*)hi)[2*i+1] = pack_h(v.z, v.w);
}

// ---- mma.sync 2-term fp16 GEMM: 128x128, 256 thr, 8 warps 2mx4n,
//      BK=32, 2-stage depth-1 prefetch, 2 CTAs/SM --------------------------
#define BM 128
#define BN 128
#define BK 32
#define SROWB 80                      // 64 B data + 16 pad
#define TILE_B (128 * SROWB)          // 10240
#define AHI_OFF  0
#define ALO_OFF  (TILE_B)
#define BHI_OFF  (2*TILE_B)
#define STAGE_B  (3*TILE_B)           // 30720
#define GEMM_SMEM (2*STAGE_B)         // 61440 -> 2 CTAs/SM
#define GTHREADS 256
#define WSZ ((size_t)D_MODEL*D_MODEL)

__global__ __launch_bounds__(GTHREADS, 2)
void gemm_mma_kernel(const __half* __restrict__ Ahi,
                     const __half* __restrict__ Alo,
                     const __half* __restrict__ Wh,
                     float* __restrict__ Cf,
                     __half* __restrict__ Qhi, __half* __restrict__ Qlo,
                     __half* __restrict__ Khi, __half* __restrict__ Vhi,
                     int qkv)
{
    extern __shared__ char smem[];
    const uint32_t sbase = smem_u32(smem);
    const int tid = threadIdx.x;
    const int wid = tid >> 5;
    const int lane = tid & 31;
    const int wm = wid & 1;           // 2 m groups of 64
    const int wn = wid >> 1;          // 4 n groups of 32

    const int z = qkv ? blockIdx.z : 0;
    const int m0 = blockIdx.y * BM;
    const int n0 = blockIdx.x * BN;

    const __half* Ah = Ahi + (size_t)m0 * 1024;
    const __half* Al = Alo + (size_t)m0 * 1024;
    const __half* Bh = Wh + (qkv ? (size_t)z * WSZ : 0) + (size_t)n0 * 1024;
    const __half* srcs[3] = {Ah, Al, Bh};

    auto load_stage = [&](int ch, int st) {
        const int k0 = ch * BK;
        const uint32_t sb = sbase + st * STAGE_B;
#pragma unroll
        for (int i = 0; i < 6; i++) {
            const int idx = tid + i * GTHREADS;   // 0..1535
            const int t3 = idx >> 9;              // tile 0..2 (512 xfers each)
            const int r = (idx >> 2) & 127;
            const int c = idx & 3;                // 4 x 16B = 64 B per row
            cp16(sb + t3 * TILE_B + (uint32_t)(r * SROWB + c * 16),
                 srcs[t3] + (size_t)r * 1024 + k0 + c * 8);
        }
        cp_commit();
    };

    float acc[4][4][4];
#pragma unroll
    for (int i = 0; i < 4; i++)
#pragma unroll
        for (int j = 0; j < 4; j++)
#pragma unroll
            for (int t = 0; t < 4; t++) acc[i][j][t] = 0.f;

    const int NCH = 1024 / BK;        // 32
    load_stage(0, 0);

    for (int ch = 0; ch < NCH; ch++) {
        asm volatile("cp.async.wait_group 0;");
        __syncthreads();              // chunk ch visible; other stage free
        if (ch + 1 < NCH) load_stage(ch + 1, (ch + 1) & 1);

        const uint32_t sb = sbase + (ch & 1) * STAGE_B;
#pragma unroll
        for (int ks = 0; ks < 2; ks++) {
            const int k16 = ks * 16;
            // B fragments resident for this k16 (4 n8 frags, hi only)
            uint32_t bhi[4][2];
#pragma unroll
            for (int nf16 = 0; nf16 < 2; nf16++) {
                const int nrow = wn * 32 + nf16 * 16 + ((lane >> 4) << 3) + (lane & 7);
                const int kc   = k16 + (((lane >> 3) & 1) << 3);
                const uint32_t off = (uint32_t)(nrow * SROWB + kc * 2);
                ldmatrix4(bhi[nf16*2][0], bhi[nf16*2][1],
                          bhi[nf16*2+1][0], bhi[nf16*2+1][1], sb + BHI_OFF + off);
            }
            // A fragments transient per mf
#pragma unroll
            for (int mf = 0; mf < 4; mf++) {
                uint32_t ahi[4], alo[4];
                const int row = wm * 64 + mf * 16 + (lane & 15);
                const int kc  = k16 + ((lane >> 4) << 3);
                const uint32_t off = (uint32_t)(row * SROWB + kc * 2);
                ldmatrix4(ahi[0], ahi[1], ahi[2], ahi[3], sb + AHI_OFF + off);
                ldmatrix4(alo[0], alo[1], alo[2], alo[3], sb + ALO_OFF + off);
#pragma unroll
                for (int nf = 0; nf < 4; nf++) {
                    mma_f16(acc[mf][nf], ahi, bhi[nf]);
                    mma_f16(acc[mf][nf], alo, bhi[nf]);
                }
            }
        }
    }

    // ---- epilogue ----
    const float scale = qkv ? (z == 0 ? 0.125f : 1.0f) : 1.0f;
    const int mode = qkv ? (z == 0 ? 1 : (z == 1 ? 2 : 3)) : 0;

#pragma unroll
    for (int mf = 0; mf < 4; mf++) {
#pragma unroll
        for (int nf = 0; nf < 4; nf++) {
            const int m_base = m0 + wm * 64 + mf * 16;
            const int n = n0 + wn * 32 + nf * 8 + (lane & 3) * 2;
            const int r0 = m_base + (lane >> 2);
            const int r1 = r0 + 8;
            const float v0 = acc[mf][nf][0] * scale;
            const float v1 = acc[mf][nf][1] * scale;
            const float v2 = acc[mf][nf][2] * scale;
            const float v3 = acc[mf][nf][3] * scale;
            if (mode == 0) {
                *(float2*)(Cf + (size_t)r0 * 1024 + n) = make_float2(v0, v1);
                *(float2*)(Cf + (size_t)r1 * 1024 + n) = make_float2(v2, v3);
            } else if (mode == 1) {          // Q: hi+lo, [bh][s][d]
                const int h = n >> 6, d = n & 63;
                const int bh0 = ((r0 >> 11) * HEADS) + h;
                const int bh1 = ((r1 >> 11) * HEADS) + h;
                store_hl(Qhi, Qlo, ((size_t)bh0 * SEQ + (r0 & 2047)) * DK + d, v0, v1);
                store_hl(Qhi, Qlo, ((size_t)bh1 * SEQ + (r1 & 2047)) * DK + d, v2, v3);
            } else if (mode == 2) {          // K: hi only, [bh][s][d]
                const int h = n >> 6, d = n & 63;
                const int bh0 = ((r0 >> 11) * HEADS) + h;
                const int bh1 = ((r1 >> 11) * HEADS) + h;
                *(__half2*)(Khi + ((size_t)bh0 * SEQ + (r0 & 2047)) * DK + d) =
                    __halves2half2(__float2half(v0), __float2half(v1));
                *(__half2*)(Khi + ((size_t)bh1 * SEQ + (r1 & 2047)) * DK + d) =
                    __halves2half2(__float2half(v2), __float2half(v3));
            } else {                         // V: hi only, transposed [bh][d][s]
                const int h = n >> 6, d = n & 63;
                const int bh0 = ((r0 >> 11) * HEADS) + h;
                const int bh1 = ((r1 >> 11) * HEADS) + h;
                const int s0 = r0 & 2047, s1 = r1 & 2047;
                Vhi[((size_t)bh0 * DK + d) * SEQ + s0] = __float2half(v0);
                Vhi[((size_t)bh0 * DK + d + 1) * SEQ + s0] = __float2half(v1);
                Vhi[((size_t)bh1 * DK + d) * SEQ + s1] = __float2half(v2);
                Vhi[((size_t)bh1 * DK + d + 1) * SEQ + s1] = __float2half(v3);
            }
        }
    }
}

// ---------------- mma.sync flash attention (causal, 2-term fp16) ------------
// 2 CTAs/SM; Q hi+lo in smem (re-read per block), K/V hi only.
#define ASTR 144
#define AQHI 0
#define AQLO 18432
#define ASTG0 36864
#define AKHI 0
#define AVHI 9216
#define ASTAGE_B 18432
#define ATT_SMEM (36864 + 2*18432)    // 73728

__global__ __launch_bounds__(256, 2)
void attn_mma_kernel(const __half* __restrict__ Qhi,
                     const __half* __restrict__ Qlo,
                     const __half* __restrict__ Khi,
                     const __half* __restrict__ Vhi,
                     __half* __restrict__ Ohi,
                     __half* __restrict__ Olo)
{
    extern __shared__ char smem[];
    const uint32_t sbase = smem_u32(smem);
    const int tid = threadIdx.x;
    const int w = tid >> 5;
    const int lane = tid & 31;
    const int qt = (int)gridDim.x - 1 - (int)blockIdx.x;  // big tiles first
    const int bh = blockIdx.y;

    const __half* Qh = Qhi + (size_t)bh * SEQ * DK + (size_t)qt * 128 * DK;
    const __half* Ql = Qlo + (size_t)bh * SEQ * DK + (size_t)qt * 128 * DK;
    const __half* Kh = Khi + (size_t)bh * SEQ * DK;
    const __half* Vh = Vhi + (size_t)bh * DK * SEQ;

    {
#pragma unroll
        for (int i = 0; i < 4; i++) {
            const int idx = tid + i * 256;
            const int row = idx >> 3, c = idx & 7;
            const uint32_t so = (uint32_t)(row * ASTR + c * 16);
            const size_t go = (size_t)row * DK + c * 8;
            cp16(sbase + AQHI + so, Qh + go);
            cp16(sbase + AQLO + so, Ql + go);
        }
        cp_commit();
    }

    const int jmax = 2 * qt + 1;
    auto load_kv = [&](int j, int st) {
        const uint32_t sb = sbase + ASTG0 + st * ASTAGE_B;
#pragma unroll
        for (int i = 0; i < 2; i++) {
            const int idx = tid + i * 256;
            const int row = idx >> 3, c = idx & 7;
            const uint32_t so = (uint32_t)(row * ASTR + c * 16);
            const size_t gk = (size_t)(j * 64 + row) * DK + c * 8;
            const size_t gv = (size_t)row * SEQ + j * 64 + c * 8;
            cp16(sb + AKHI + so, Kh + gk);
            cp16(sb + AVHI + so, Vh + gv);
        }
        cp_commit();
    };

    load_kv(0, 0);
    asm volatile("cp.async.wait_group 1;");
    __syncthreads();

    float o[8][4];
#pragma unroll
    for (int nf = 0; nf < 8; nf++)
#pragma unroll
        for (int t = 0; t < 4; t++) o[nf][t] = 0.f;
    float mA = -1e30f, mB = -1e30f, lA = 0.f, lB = 0.f;

    const int rowA_g = qt * 128 + w * 16 + (lane >> 2);
    const int rowB_g = rowA_g + 8;

    for (int j = 0; j <= jmax; j++) {
        if (j < jmax) load_kv(j + 1, (j + 1) & 1);
        if (j < jmax) asm volatile("cp.async.wait_group 1;");
        else          asm volatile("cp.async.wait_group 0;");
        __syncthreads();

        const uint32_t sb = sbase + ASTG0 + (j & 1) * ASTAGE_B;

        float s[8][4];
#pragma unroll
        for (int nf = 0; nf < 8; nf++)
#pragma unroll
            for (int t = 0; t < 4; t++) s[nf][t] = 0.f;
#pragma unroll
        for (int kb = 0; kb < 4; kb++) {
            uint32_t qh[4], ql[4];
            {
                const int row = w * 16 + (lane & 15);
                const int kc = kb * 16 + ((lane >> 4) << 3);
                const uint32_t off = (uint32_t)(row * ASTR + kc * 2);
                ldmatrix4(qh[0], qh[1], qh[2], qh[3], sbase + AQHI + off);
                ldmatrix4(ql[0], ql[1], ql[2], ql[3], sbase + AQLO + off);
            }
            uint32_t kh[8][2];
            const uint32_t kcoff = (uint32_t)((kb * 16 + (((lane >> 3) & 1) << 3)) * 2);
            const int nr = ((lane >> 4) << 3) + (lane & 7);
#pragma unroll
            for (int ng = 0; ng < 4; ng++) {
                const uint32_t off = (uint32_t)((ng * 16 + nr) * ASTR) + kcoff;
                ldmatrix4(kh[2*ng][0], kh[2*ng][1], kh[2*ng+1][0], kh[2*ng+1][1],
                          sb + AKHI + off);
            }
#pragma unroll
            for (int nf = 0; nf < 8; nf++) {
                mma_f16(s[nf], qh, kh[nf]);
                mma_f16(s[nf], ql, kh[nf]);
            }
        }

        if (j >= 2 * qt) {
#pragma unroll
            for (int nf = 0; nf < 8; nf++) {
                const int c0 = j * 64 + nf * 8 + (lane & 3) * 2;
                if (c0 > rowA_g)     s[nf][0] = -1e30f;
                if (c0 + 1 > rowA_g) s[nf][1] = -1e30f;
                if (c0 > rowB_g)     s[nf][2] = -1e30f;
                if (c0 + 1 > rowB_g) s[nf][3] = -1e30f;
            }
        }

        float bmA = -1e30f, bmB = -1e30f;
#pragma unroll
        for (int nf = 0; nf < 8; nf++) {
            bmA = fmaxf(bmA, fmaxf(s[nf][0], s[nf][1]));
            bmB = fmaxf(bmB, fmaxf(s[nf][2], s[nf][3]));
        }
        bmA = fmaxf(bmA, __shfl_xor_sync(0xffffffffu, bmA, 1));
        bmA = fmaxf(bmA, __shfl_xor_sync(0xffffffffu, bmA, 2));
        bmB = fmaxf(bmB, __shfl_xor_sync(0xffffffffu, bmB, 1));
        bmB = fmaxf(bmB, __shfl_xor_sync(0xffffffffu, bmB, 2));
        const float mnA = fmaxf(mA, bmA);
        const float mnB = fmaxf(mB, bmB);
        const float alA = __expf(mA - mnA);
        const float alB = __expf(mB - mnB);
        mA = mnA; mB = mnB;

        float sumA = 0.f, sumB = 0.f;
#pragma unroll
        for (int nf = 0; nf < 8; nf++) {
            s[nf][0] = __expf(s[nf][0] - mnA);
            s[nf][1] = __expf(s[nf][1] - mnA);
            s[nf][2] = __expf(s[nf][2] - mnB);
            s[nf][3] = __expf(s[nf][3] - mnB);
            sumA += s[nf][0] + s[nf][1];
            sumB += s[nf][2] + s[nf][3];
        }
        sumA += __shfl_xor_sync(0xffffffffu, sumA, 1);
        sumA += __shfl_xor_sync(0xffffffffu, sumA, 2);
        sumB += __shfl_xor_sync(0xffffffffu, sumB, 1);
        sumB += __shfl_xor_sync(0xffffffffu, sumB, 2);
        lA = lA * alA + sumA;
        lB = lB * alB + sumB;

#pragma unroll
        for (int nf = 0; nf < 8; nf++) {
            o[nf][0] *= alA; o[nf][1] *= alA;
            o[nf][2] *= alB; o[nf][3] *= alB;
        }

        // P fragments: fp16 hi + residual lo (A-side correction for PV)
        uint32_t pf_hi[4][4], pf_lo[4][4];
#pragma unroll
        for (int t = 0; t < 4; t++) {
            float r0, r1;
            pf_hi[t][0] = pack_hi_h(s[2*t][0],   s[2*t][1],   r0, r1); pf_lo[t][0] = pack_h(r0, r1);
            pf_hi[t][1] = pack_hi_h(s[2*t][2],   s[2*t][3],   r0, r1); pf_lo[t][1] = pack_h(r0, r1);
            pf_hi[t][2] = pack_hi_h(s[2*t+1][0], s[2*t+1][1], r0, r1); pf_lo[t][2] = pack_h(r0, r1);
            pf_hi[t][3] = pack_hi_h(s[2*t+1][2], s[2*t+1][3], r0, r1); pf_lo[t][3] = pack_h(r0, r1);
        }

#pragma unroll
        for (int t = 0; t < 4; t++) {
            uint32_t vh[8][2];
            const uint32_t kcoff = (uint32_t)((t * 16 + (((lane >> 3) & 1) << 3)) * 2);
            const int nr = ((lane >> 4) << 3) + (lane & 7);
#pragma unroll
            for (int ng = 0; ng < 4; ng++) {
                const uint32_t off = (uint32_t)((ng * 16 + nr) * ASTR) + kcoff;
                ldmatrix4(vh[2*ng][0], vh[2*ng][1], vh[2*ng+1][0], vh[2*ng+1][1],
                          sb + AVHI + off);
            }
#pragma unroll
            for (int nf = 0; nf < 8; nf++) {
                mma_f16(o[nf], pf_hi[t], vh[nf]);
                mma_f16(o[nf], pf_lo[t], vh[nf]);
            }
        }
        __syncthreads();
    }

    const float invA = 1.f / lA;
    const float invB = 1.f / lB;
    const int b = bh >> 4, h = bh & 15;
    const size_t mAi = (size_t)(b * SEQ) + (size_t)(rowA_g & 2047);
    const size_t mBi = mAi + 8;
#pragma unroll
    for (int nf = 0; nf < 8; nf++) {
        const int col = h * 64 + nf * 8 + (lane & 3) * 2;
        store_hl(Ohi, Olo, mAi * D_MODEL + col, o[nf][0] * invA, o[nf][1] * invA);
        store_hl(Ohi, Olo, mBi * D_MODEL + col, o[nf][2] * invB, o[nf][3] * invB);
    }
}

// ---------------------------------------------------------------------------
extern "C" void kernel_launch(void* const* d_in, const int* in_sizes, int n_in,
                              void* d_out, int out_size)
{
    (void)in_sizes; (void)n_in; (void)out_size;
    const float* x  = (const float*)d_in[0];
    const float* Wq = (const float*)d_in[1];
    const float* Wk = (const float*)d_in[2];
    const float* Wv = (const float*)d_in[3];
    const float* Wo = (const float*)d_in[4];
    float* out = (float*)d_out;

    __half *xhi, *xlo, *whi;
    __half *qhi, *qlo, *khi, *vhi, *ahi, *alo;
    cudaGetSymbolAddress((void**)&xhi, g_xhi);
    cudaGetSymbolAddress((void**)&xlo, g_xlo);
    cudaGetSymbolAddress((void**)&whi, g_whi);
    cudaGetSymbolAddress((void**)&qhi, g_qhi);
    cudaGetSymbolAddress((void**)&qlo, g_qlo);
    cudaGetSymbolAddress((void**)&khi, g_khi);
    cudaGetSymbolAddress((void**)&vhi, g_vhi);
    cudaGetSymbolAddress((void**)&ahi, g_ahi);
    cudaGetSymbolAddress((void**)&alo, g_alo);

    cudaFuncSetAttribute(gemm_mma_kernel,
                         cudaFuncAttributeMaxDynamicSharedMemorySize, GEMM_SMEM);
    cudaFuncSetAttribute(attn_mma_kernel,
                         cudaFuncAttributeMaxDynamicSharedMemorySize, ATT_SMEM);

    const int WN4 = D_MODEL * D_MODEL / 4;
    const int XN4 = MTOT * D_MODEL / 4;

    split_kernel<<<XN4 / 256, 256>>>(x, xhi, xlo, XN4);
    conv_w_kernel<<<dim3(WN4 / 256, 1, 4), 256>>>(Wq, Wk, Wv, Wo, whi, WN4);

    // fused Q/K/V projections (blockIdx.z selects weight & output)
    dim3 gq(D_MODEL / BN, MTOT / BM, 3);     // (8, 64, 3)
    gemm_mma_kernel<<<gq, GTHREADS, GEMM_SMEM>>>(xhi, xlo, whi,
                                            nullptr, qhi, qlo, khi, vhi, 1);

    attn_mma_kernel<<<dim3(SEQ / 128, BH), 256, ATT_SMEM>>>(qhi, qlo, khi, vhi,
                                                            ahi, alo);

    // output projection
    dim3 go(D_MODEL / BN, MTOT / BM, 1);     // (8, 64)
    gemm_mma_kernel<<<go, GTHREADS, GEMM_SMEM>>>(ahi, alo, whi + 3*WSZ,
                                            out, qhi, qlo, khi, vhi, 0);
}

// round 15
// speedup vs baseline: 1.4388x; 1.0115x over previous
#include <cuda_runtime.h>
#include <cuda_fp16.h>
#include <cstdint>

#define D_MODEL 1024
#define HEADS   16
#define DK      64
#define SEQ     2048
#define BATCH   4
#define BH      (BATCH*HEADS)
#define MTOT    (BATCH*SEQ)          // 8192

// ---------------- scratch (device globals: allocation-free) ----------------
__device__ __half g_xhi[MTOT*D_MODEL];
__device__ __half g_xlo[MTOT*D_MODEL];
__device__ __half g_whi[4][D_MODEL*D_MODEL];
__device__ __half g_qhi[BH*SEQ*DK];
__device__ __half g_qlo[BH*SEQ*DK];
__device__ __half g_khi[BH*SEQ*DK];
__device__ __half g_vhi[BH*DK*SEQ];   // transposed [bh][d][s]
__device__ __half g_ahi[MTOT*D_MODEL];
__device__ __half g_alo[MTOT*D_MODEL];

// ---------------- helpers ----------------
__device__ __forceinline__ uint32_t smem_u32(const void* p) {
    uint32_t a;
    asm("{ .reg .u64 t; cvta.to.shared.u64 t, %1; cvt.u32.u64 %0, t; }"
        : "=r"(a) : "l"(p));
    return a;
}
__device__ __forceinline__ void cp16(uint32_t saddr, const void* gaddr) {
    asm volatile("cp.async.cg.shared.global [%0], [%1], 16;"
                 :: "r"(saddr), "l"(gaddr));
}
__device__ __forceinline__ void cp_commit() {
    asm volatile("cp.async.commit_group;");
}
__device__ __forceinline__ void ldmatrix4(uint32_t& r0, uint32_t& r1,
                                          uint32_t& r2, uint32_t& r3, uint32_t addr) {
    asm volatile("ldmatrix.sync.aligned.m8n8.x4.shared.b16 {%0,%1,%2,%3}, [%4];"
                 : "=r"(r0), "=r"(r1), "=r"(r2), "=r"(r3) : "r"(addr));
}
__device__ __forceinline__ void mma_f16(float* c, const uint32_t* a, const uint32_t* b) {
    asm volatile("mma.sync.aligned.m16n8k16.row.col.f32.f16.f16.f32 "
                 "{%0,%1,%2,%3}, {%4,%5,%6,%7}, {%8,%9}, {%0,%1,%2,%3};"
                 : "+f"(c[0]), "+f"(c[1]), "+f"(c[2]), "+f"(c[3])
                 : "r"(a[0]), "r"(a[1]), "r"(a[2]), "r"(a[3]),
                   "r"(b[0]), "r"(b[1]));
}
__device__ __forceinline__ uint32_t pack_hi_h(float a, float b, float& ra, float& rb) {
    __half h0 = __float2half(a);
    __half h1 = __float2half(b);
    ra = a - __half2float(h0);
    rb = b - __half2float(h1);
    __half2 t = __halves2half2(h0, h1);
    return *(uint32_t*)&t;
}
__device__ __forceinline__ uint32_t pack_h(float a, float b) {
    __half2 t = __halves2half2(__float2half(a), __float2half(b));
    return *(uint32_t*)&t;
}
__device__ __forceinline__ void store_hl(__half* hi, __half* lo,
                                         size_t idx, float v0, float v1) {
    __half h0 = __float2half(v0);
    __half h1 = __float2half(v1);
    *(__half2*)(hi + idx) = __halves2half2(h0, h1);
    *(__half2*)(lo + idx) = __halves2half2(
        __float2half(v0 - __half2float(h0)),
        __float2half(v1 - __half2float(h1)));
}

// ---------------- split fp32 -> (hi, lo) fp16 ----------------
__global__ void split_kernel(const float* __restrict__ in,
                             __half* __restrict__ hi,
                             __half* __restrict__ lo, int n4)
{
    int i = blockIdx.x * blockDim.x + threadIdx.x;
    if (i >= n4) return;
    float4 v = ((const float4*)in)[i];
    float r0, r1, r2, r3;
    uint32_t h01 = pack_hi_h(v.x, v.y, r0, r1);
    uint32_t h23 = pack_hi_h(v.z, v.w, r2, r3);
    ((uint32_t*)hi)[2*i+0] = h01;
    ((uint32_t*)hi)[2*i+1] = h23;
    ((uint32_t*)lo)[2*i+0] = pack_h(r0, r1);
    ((uint32_t*)lo)[2*i+1] = pack_h(r2, r3);
}

// fused weight convert: hi only (B-side correction dropped, fp16 2-term)
__global__ void conv_w_kernel(const float* __restrict__ W0,
                              const float* __restrict__ W1,
                              const float* __restrict__ W2,
                              const float* __restrict__ W3,
                              __half* __restrict__ hi, int n4)
{
    const int z = blockIdx.z;
    const float* in = (z == 0) ? W0 : (z == 1) ? W1 : (z == 2) ? W2 : W3;
    hi += (size_t)z * D_MODEL * D_MODEL;
    int i = blockIdx.x * blockDim.x + threadIdx.x;
    if (i >= n4) return;
    float4 v = ((const float4*)in)[i];
    ((uint32_t*)hi)[2*i+0] = pack_h(v.x, v.y);
    ((uint32_t*)hi)[2*i+1] = pack_h(v.z, v.w);
}

// ---- mma.sync 2-term fp16 GEMM: 128x128, 256 thr, 8 warps 4m x 2n
//      (warp tile 32x64), BK=32, 3-stage depth-2 prefetch, 2 CTAs/SM -------
#define BM 128
#define BN 128
#define BK 32
#define SROWB 80                      // 64 B data + 16 pad
#define TILE_B (128 * SROWB)          // 10240
#define AHI_OFF  0
#define ALO_OFF  (TILE_B)
#define BHI_OFF  (2*TILE_B)
#define STAGE_B  (3*TILE_B)           // 30720
#define NSTAGE 3
#define GEMM_SMEM (NSTAGE*STAGE_B)    // 92160 -> 2 CTAs/SM (184320 <= 227KB)
#define GTHREADS 256
#define WSZ ((size_t)D_MODEL*D_MODEL)

__global__ __launch_bounds__(GTHREADS, 2)
void gemm_mma_kernel(const __half* __restrict__ Ahi,
                     const __half* __restrict__ Alo,
                     const __half* __restrict__ Wh,
                     float* __restrict__ Cf,
                     __half* __restrict__ Qhi, __half* __restrict__ Qlo,
                     __half* __restrict__ Khi, __half* __restrict__ Vhi,
                     int qkv)
{
    extern __shared__ char smem[];
    const uint32_t sbase = smem_u32(smem);
    const int tid = threadIdx.x;
    const int wid = tid >> 5;
    const int lane = tid & 31;
    const int wm = wid & 3;           // 4 m groups of 32
    const int wn = wid >> 2;          // 2 n groups of 64

    const int z = qkv ? blockIdx.z : 0;
    const int m0 = blockIdx.y * BM;
    const int n0 = blockIdx.x * BN;

    const __half* Ah = Ahi + (size_t)m0 * 1024;
    const __half* Al = Alo + (size_t)m0 * 1024;
    const __half* Bh = Wh + (qkv ? (size_t)z * WSZ : 0) + (size_t)n0 * 1024;
    const __half* srcs[3] = {Ah, Al, Bh};

    auto load_stage = [&](int ch, int st) {
        const int k0 = ch * BK;
        const uint32_t sb = sbase + st * STAGE_B;
#pragma unroll
        for (int i = 0; i < 6; i++) {
            const int idx = tid + i * GTHREADS;   // 0..1535
            const int t3 = idx >> 9;              // tile 0..2 (512 xfers each)
            const int r = (idx >> 2) & 127;
            const int c = idx & 3;                // 4 x 16B = 64 B per row
            cp16(sb + t3 * TILE_B + (uint32_t)(r * SROWB + c * 16),
                 srcs[t3] + (size_t)r * 1024 + k0 + c * 8);
        }
        cp_commit();
    };

    float acc[2][8][4];
#pragma unroll
    for (int i = 0; i < 2; i++)
#pragma unroll
        for (int j = 0; j < 8; j++)
#pragma unroll
            for (int t = 0; t < 4; t++) acc[i][j][t] = 0.f;

    const int NCH = 1024 / BK;        // 32
    load_stage(0, 0);
    load_stage(1, 1);

    for (int ch = 0; ch < NCH; ch++) {
        if (ch + 1 < NCH) asm volatile("cp.async.wait_group 1;");
        else              asm volatile("cp.async.wait_group 0;");
        __syncthreads();              // chunk ch ready; stage (ch+2)%3 free
        if (ch + 2 < NCH) load_stage(ch + 2, (ch + 2) % NSTAGE);

        const uint32_t sb = sbase + (ch % NSTAGE) * STAGE_B;
#pragma unroll
        for (int ks = 0; ks < 2; ks++) {
            const int k16 = ks * 16;
            // B fragments resident for this k16 (8 n8 frags, hi only)
            uint32_t bhi[8][2];
#pragma unroll
            for (int nf16 = 0; nf16 < 4; nf16++) {
                const int nrow = wn * 64 + nf16 * 16 + ((lane >> 4) << 3) + (lane & 7);
                const int kc   = k16 + (((lane >> 3) & 1) << 3);
                const uint32_t off = (uint32_t)(nrow * SROWB + kc * 2);
                ldmatrix4(bhi[nf16*2][0], bhi[nf16*2][1],
                          bhi[nf16*2+1][0], bhi[nf16*2+1][1], sb + BHI_OFF + off);
            }
            // A fragments transient per mf
#pragma unroll
            for (int mf = 0; mf < 2; mf++) {
                uint32_t ahi[4], alo[4];
                const int row = wm * 32 + mf * 16 + (lane & 15);
                const int kc  = k16 + ((lane >> 4) << 3);
                const uint32_t off = (uint32_t)(row * SROWB + kc * 2);
                ldmatrix4(ahi[0], ahi[1], ahi[2], ahi[3], sb + AHI_OFF + off);
                ldmatrix4(alo[0], alo[1], alo[2], alo[3], sb + ALO_OFF + off);
#pragma unroll
                for (int nf = 0; nf < 8; nf++) {
                    mma_f16(acc[mf][nf], ahi, bhi[nf]);
                    mma_f16(acc[mf][nf], alo, bhi[nf]);
                }
            }
        }
    }

    // ---- epilogue ----
    // Q pre-scaled by (1/8)*log2(e) for log2-domain softmax
    const float scale = qkv ? (z == 0 ? 0.1803368801111137f : 1.0f) : 1.0f;
    const int mode = qkv ? (z == 0 ? 1 : (z == 1 ? 2 : 3)) : 0;

#pragma unroll
    for (int mf = 0; mf < 2; mf++) {
#pragma unroll
        for (int nf = 0; nf < 8; nf++) {
            const int m_base = m0 + wm * 32 + mf * 16;
            const int n = n0 + wn * 64 + nf * 8 + (lane & 3) * 2;
            const int r0 = m_base + (lane >> 2);
            const int r1 = r0 + 8;
            const float v0 = acc[mf][nf][0] * scale;
            const float v1 = acc[mf][nf][1] * scale;
            const float v2 = acc[mf][nf][2] * scale;
            const float v3 = acc[mf][nf][3] * scale;
            if (mode == 0) {
                *(float2*)(Cf + (size_t)r0 * 1024 + n) = make_float2(v0, v1);
                *(float2*)(Cf + (size_t)r1 * 1024 + n) = make_float2(v2, v3);
            } else if (mode == 1) {          // Q: hi+lo, [bh][s][d]
                const int h = n >> 6, d = n & 63;
                const int bh0 = ((r0 >> 11) * HEADS) + h;
                const int bh1 = ((r1 >> 11) * HEADS) + h;
                store_hl(Qhi, Qlo, ((size_t)bh0 * SEQ + (r0 & 2047)) * DK + d, v0, v1);
                store_hl(Qhi, Qlo, ((size_t)bh1 * SEQ + (r1 & 2047)) * DK + d, v2, v3);
            } else if (mode == 2) {          // K: hi only, [bh][s][d]
                const int h = n >> 6, d = n & 63;
                const int bh0 = ((r0 >> 11) * HEADS) + h;
                const int bh1 = ((r1 >> 11) * HEADS) + h;
                *(__half2*)(Khi + ((size_t)bh0 * SEQ + (r0 & 2047)) * DK + d) =
                    __halves2half2(__float2half(v0), __float2half(v1));
                *(__half2*)(Khi + ((size_t)bh1 * SEQ + (r1 & 2047)) * DK + d) =
                    __halves2half2(__float2half(v2), __float2half(v3));
            } else {                         // V: hi only, transposed [bh][d][s]
                const int h = n >> 6, d = n & 63;
                const int bh0 = ((r0 >> 11) * HEADS) + h;
                const int bh1 = ((r1 >> 11) * HEADS) + h;
                const int s0 = r0 & 2047, s1 = r1 & 2047;
                Vhi[((size_t)bh0 * DK + d) * SEQ + s0] = __float2half(v0);
                Vhi[((size_t)bh0 * DK + d + 1) * SEQ + s0] = __float2half(v1);
                Vhi[((size_t)bh1 * DK + d) * SEQ + s1] = __float2half(v2);
                Vhi[((size_t)bh1 * DK + d + 1) * SEQ + s1] = __float2half(v3);
            }
        }
    }
}

// ---------------- mma.sync flash attention (causal, 2-term fp16) ------------
// 2 CTAs/SM; Q hi+lo in smem (re-read per block), K/V hi only.
// Scores arrive in log2 domain (Q pre-scaled by 0.125*log2e) -> exp2f softmax.
#define ASTR 144
#define AQHI 0
#define AQLO 18432
#define ASTG0 36864
#define AKHI 0
#define AVHI 9216
#define ASTAGE_B 18432
#define ATT_SMEM (36864 + 2*18432)    // 73728

__global__ __launch_bounds__(256, 2)
void attn_mma_kernel(const __half* __restrict__ Qhi,
                     const __half* __restrict__ Qlo,
                     const __half* __restrict__ Khi,
                     const __half* __restrict__ Vhi,
                     __half* __restrict__ Ohi,
                     __half* __restrict__ Olo)
{
    extern __shared__ char smem[];
    const uint32_t sbase = smem_u32(smem);
    const int tid = threadIdx.x;
    const int w = tid >> 5;
    const int lane = tid & 31;
    const int qt = (int)gridDim.x - 1 - (int)blockIdx.x;  // big tiles first
    const int bh = blockIdx.y;

    const __half* Qh = Qhi + (size_t)bh * SEQ * DK + (size_t)qt * 128 * DK;
    const __half* Ql = Qlo + (size_t)bh * SEQ * DK + (size_t)qt * 128 * DK;
    const __half* Kh = Khi + (size_t)bh * SEQ * DK;
    const __half* Vh = Vhi + (size_t)bh * DK * SEQ;

    {
#pragma unroll
        for (int i = 0; i < 4; i++) {
            const int idx = tid + i * 256;
            const int row = idx >> 3, c = idx & 7;
            const uint32_t so = (uint32_t)(row * ASTR + c * 16);
            const size_t go = (size_t)row * DK + c * 8;
            cp16(sbase + AQHI + so, Qh + go);
            cp16(sbase + AQLO + so, Ql + go);
        }
        cp_commit();
    }

    const int jmax = 2 * qt + 1;
    auto load_kv = [&](int j, int st) {
        const uint32_t sb = sbase + ASTG0 + st * ASTAGE_B;
#pragma unroll
        for (int i = 0; i < 2; i++) {
            const int idx = tid + i * 256;
            const int row = idx >> 3, c = idx & 7;
            const uint32_t so = (uint32_t)(row * ASTR + c * 16);
            const size_t gk = (size_t)(j * 64 + row) * DK + c * 8;
            const size_t gv = (size_t)row * SEQ + j * 64 + c * 8;
            cp16(sb + AKHI + so, Kh + gk);
            cp16(sb + AVHI + so, Vh + gv);
        }
        cp_commit();
    };

    load_kv(0, 0);
    asm volatile("cp.async.wait_group 1;");
    __syncthreads();

    float o[8][4];
#pragma unroll
    for (int nf = 0; nf < 8; nf++)
#pragma unroll
        for (int t = 0; t < 4; t++) o[nf][t] = 0.f;
    float mA = -1e30f, mB = -1e30f, lA = 0.f, lB = 0.f;

    const int rowA_g = qt * 128 + w * 16 + (lane >> 2);
    const int rowB_g = rowA_g + 8;

    for (int j = 0; j <= jmax; j++) {
        if (j < jmax) load_kv(j + 1, (j + 1) & 1);
        if (j < jmax) asm volatile("cp.async.wait_group 1;");
        else          asm volatile("cp.async.wait_group 0;");
        __syncthreads();

        const uint32_t sb = sbase + ASTG0 + (j & 1) * ASTAGE_B;

        float s[8][4];
#pragma unroll
        for (int nf = 0; nf < 8; nf++)
#pragma unroll
            for (int t = 0; t < 4; t++) s[nf][t] = 0.f;
#pragma unroll
        for (int kb = 0; kb < 4; kb++) {
            uint32_t qh[4], ql[4];
            {
                const int row = w * 16 + (lane & 15);
                const int kc = kb * 16 + ((lane >> 4) << 3);
                const uint32_t off = (uint32_t)(row * ASTR + kc * 2);
                ldmatrix4(qh[0], qh[1], qh[2], qh[3], sbase + AQHI + off);
                ldmatrix4(ql[0], ql[1], ql[2], ql[3], sbase + AQLO + off);
            }
            uint32_t kh[8][2];
            const uint32_t kcoff = (uint32_t)((kb * 16 + (((lane >> 3) & 1) << 3)) * 2);
            const int nr = ((lane >> 4) << 3) + (lane & 7);
#pragma unroll
            for (int ng = 0; ng < 4; ng++) {
                const uint32_t off = (uint32_t)((ng * 16 + nr) * ASTR) + kcoff;
                ldmatrix4(kh[2*ng][0], kh[2*ng][1], kh[2*ng+1][0], kh[2*ng+1][1],
                          sb + AKHI + off);
            }
#pragma unroll
            for (int nf = 0; nf < 8; nf++) {
                mma_f16(s[nf], qh, kh[nf]);
                mma_f16(s[nf], ql, kh[nf]);
            }
        }

        if (j >= 2 * qt) {
#pragma unroll
            for (int nf = 0; nf < 8; nf++) {
                const int c0 = j * 64 + nf * 8 + (lane & 3) * 2;
                if (c0 > rowA_g)     s[nf][0] = -1e30f;
                if (c0 + 1 > rowA_g) s[nf][1] = -1e30f;
                if (c0 > rowB_g)     s[nf][2] = -1e30f;
                if (c0 + 1 > rowB_g) s[nf][3] = -1e30f;
            }
        }

        float bmA = -1e30f, bmB = -1e30f;
#pragma unroll
        for (int nf = 0; nf < 8; nf++) {
            bmA = fmaxf(bmA, fmaxf(s[nf][0], s[nf][1]));
            bmB = fmaxf(bmB, fmaxf(s[nf][2], s[nf][3]));
        }
        bmA = fmaxf(bmA, __shfl_xor_sync(0xffffffffu, bmA, 1));
        bmA = fmaxf(bmA, __shfl_xor_sync(0xffffffffu, bmA, 2));
        bmB = fmaxf(bmB, __shfl_xor_sync(0xffffffffu, bmB, 1));
        bmB = fmaxf(bmB, __shfl_xor_sync(0xffffffffu, bmB, 2));
        const float mnA = fmaxf(mA, bmA);
        const float mnB = fmaxf(mB, bmB);
        const float alA = exp2f(mA - mnA);
        const float alB = exp2f(mB - mnB);
        mA = mnA; mB = mnB;

        float sumA = 0.f, sumB = 0.f;
#pragma unroll
        for (int nf = 0; nf < 8; nf++) {
            s[nf][0] = exp2f(s[nf][0] - mnA);
            s[nf][1] = exp2f(s[nf][1] - mnA);
            s[nf][2] = exp2f(s[nf][2] - mnB);
            s[nf][3] = exp2f(s[nf][3] - mnB);
            sumA += s[nf][0] + s[nf][1];
            sumB += s[nf][2] + s[nf][3];
        }
        sumA += __shfl_xor_sync(0xffffffffu, sumA, 1);
        sumA += __shfl_xor_sync(0xffffffffu, sumA, 2);
        sumB += __shfl_xor_sync(0xffffffffu, sumB, 1);
        sumB += __shfl_xor_sync(0xffffffffu, sumB, 2);
        lA = lA * alA + sumA;
        lB = lB * alB + sumB;

#pragma unroll
        for (int nf = 0; nf < 8; nf++) {
            o[nf][0] *= alA; o[nf][1] *= alA;
            o[nf][2] *= alB; o[nf][3] *= alB;
        }

        // P fragments: fp16 hi + residual lo (A-side correction for PV)
        uint32_t pf_hi[4][4], pf_lo[4][4];
#pragma unroll
        for (int t = 0; t < 4; t++) {
            float r0, r1;
            pf_hi[t][0] = pack_hi_h(s[2*t][0],   s[2*t][1],   r0, r1); pf_lo[t][0] = pack_h(r0, r1);
            pf_hi[t][1] = pack_hi_h(s[2*t][2],   s[2*t][3],   r0, r1); pf_lo[t][1] = pack_h(r0, r1);
            pf_hi[t][2] = pack_hi_h(s[2*t+1][0], s[2*t+1][1], r0, r1); pf_lo[t][2] = pack_h(r0, r1);
            pf_hi[t][3] = pack_hi_h(s[2*t+1][2], s[2*t+1][3], r0, r1); pf_lo[t][3] = pack_h(r0, r1);
        }

#pragma unroll
        for (int t = 0; t < 4; t++) {
            uint32_t vh[8][2];
            const uint32_t kcoff = (uint32_t)((t * 16 + (((lane >> 3) & 1) << 3)) * 2);
            const int nr = ((lane >> 4) << 3) + (lane & 7);
#pragma unroll
            for (int ng = 0; ng < 4; ng++) {
                const uint32_t off = (uint32_t)((ng * 16 + nr) * ASTR) + kcoff;
                ldmatrix4(vh[2*ng][0], vh[2*ng][1], vh[2*ng+1][0], vh[2*ng+1][1],
                          sb + AVHI + off);
            }
#pragma unroll
            for (int nf = 0; nf < 8; nf++) {
                mma_f16(o[nf], pf_hi[t], vh[nf]);
                mma_f16(o[nf], pf_lo[t], vh[nf]);
            }
        }
        __syncthreads();
    }

    const float invA = 1.f / lA;
    const float invB = 1.f / lB;
    const int b = bh >> 4, h = bh & 15;
    const size_t mAi = (size_t)(b * SEQ) + (size_t)(rowA_g & 2047);
    const size_t mBi = mAi + 8;
#pragma unroll
    for (int nf = 0; nf < 8; nf++) {
        const int col = h * 64 + nf * 8 + (lane & 3) * 2;
        store_hl(Ohi, Olo, mAi * D_MODEL + col, o[nf][0] * invA, o[nf][1] * invA);
        store_hl(Ohi, Olo, mBi * D_MODEL + col, o[nf][2] * invB, o[nf][3] * invB);
    }
}

// ---------------------------------------------------------------------------
extern "C" void kernel_launch(void* const* d_in, const int* in_sizes, int n_in,
                              void* d_out, int out_size)
{
    (void)in_sizes; (void)n_in; (void)out_size;
    const float* x  = (const float*)d_in[0];
    const float* Wq = (const float*)d_in[1];
    const float* Wk = (const float*)d_in[2];
    const float* Wv = (const float*)d_in[3];
    const float* Wo = (const float*)d_in[4];
    float* out = (float*)d_out;

    __half *xhi, *xlo, *whi;
    __half *qhi, *qlo, *khi, *vhi, *ahi, *alo;
    cudaGetSymbolAddress((void**)&xhi, g_xhi);
    cudaGetSymbolAddress((void**)&xlo, g_xlo);
    cudaGetSymbolAddress((void**)&whi, g_whi);
    cudaGetSymbolAddress((void**)&qhi, g_qhi);
    cudaGetSymbolAddress((void**)&qlo, g_qlo);
    cudaGetSymbolAddress((void**)&khi, g_khi);
    cudaGetSymbolAddress((void**)&vhi, g_vhi);
    cudaGetSymbolAddress((void**)&ahi, g_ahi);
    cudaGetSymbolAddress((void**)&alo, g_alo);

    cudaFuncSetAttribute(gemm_mma_kernel,
                         cudaFuncAttributeMaxDynamicSharedMemorySize, GEMM_SMEM);
    cudaFuncSetAttribute(attn_mma_kernel,
                         cudaFuncAttributeMaxDynamicSharedMemorySize, ATT_SMEM);

    const int WN4 = D_MODEL * D_MODEL / 4;
    const int XN4 = MTOT * D_MODEL / 4;

    split_kernel<<<XN4 / 256, 256>>>(x, xhi, xlo, XN4);
    conv_w_kernel<<<dim3(WN4 / 256, 1, 4), 256>>>(Wq, Wk, Wv, Wo, whi, WN4);

    // fused Q/K/V projections (blockIdx.z selects weight & output)
    dim3 gq(D_MODEL / BN, MTOT / BM, 3);     // (8, 64, 3)
    gemm_mma_kernel<<<gq, GTHREADS, GEMM_SMEM>>>(xhi, xlo, whi,
                                            nullptr, qhi, qlo, khi, vhi, 1);

    attn_mma_kernel<<<dim3(SEQ / 128, BH), 256, ATT_SMEM>>>(qhi, qlo, khi, vhi,
                                                            ahi, alo);

    // output projection
    dim3 go(D_MODEL / BN, MTOT / BM, 1);     // (8, 64)
    gemm_mma_kernel<<<go, GTHREADS, GEMM_SMEM>>>(ahi, alo, whi + 3*WSZ,
                                            out, qhi, qlo, khi, vhi, 0);
}

// round 16
// speedup vs baseline: 1.5615x; 1.0852x over previous
#include <cuda_runtime.h>
#include <cuda_fp16.h>
#include <cstdint>

#define D_MODEL 1024
#define HEADS   16
#define DK      64
#define SEQ     2048
#define BATCH   4
#define BH      (BATCH*HEADS)
#define MTOT    (BATCH*SEQ)          // 8192

// ---------------- scratch (device globals: allocation-free) ----------------
__device__ __half g_xhi[MTOT*D_MODEL];
__device__ __half g_xlo[MTOT*D_MODEL];
__device__ __half g_whi[4][D_MODEL*D_MODEL];
__device__ __half g_qhi[BH*SEQ*DK];
__device__ __half g_qlo[BH*SEQ*DK];
__device__ __half g_khi[BH*SEQ*DK];
__device__ __half g_vhi[BH*DK*SEQ];   // transposed [bh][d][s]
__device__ __half g_ahi[MTOT*D_MODEL];

// ---------------- helpers ----------------
__device__ __forceinline__ uint32_t smem_u32(const void* p) {
    uint32_t a;
    asm("{ .reg .u64 t; cvta.to.shared.u64 t, %1; cvt.u32.u64 %0, t; }"
        : "=r"(a) : "l"(p));
    return a;
}
__device__ __forceinline__ void cp16(uint32_t saddr, const void* gaddr) {
    asm volatile("cp.async.cg.shared.global [%0], [%1], 16;"
                 :: "r"(saddr), "l"(gaddr));
}
__device__ __forceinline__ void cp_commit() {
    asm volatile("cp.async.commit_group;");
}
__device__ __forceinline__ void ldmatrix4(uint32_t& r0, uint32_t& r1,
                                          uint32_t& r2, uint32_t& r3, uint32_t addr) {
    asm volatile("ldmatrix.sync.aligned.m8n8.x4.shared.b16 {%0,%1,%2,%3}, [%4];"
                 : "=r"(r0), "=r"(r1), "=r"(r2), "=r"(r3) : "r"(addr));
}
__device__ __forceinline__ void mma_f16(float* c, const uint32_t* a, const uint32_t* b) {
    asm volatile("mma.sync.aligned.m16n8k16.row.col.f32.f16.f16.f32 "
                 "{%0,%1,%2,%3}, {%4,%5,%6,%7}, {%8,%9}, {%0,%1,%2,%3};"
                 : "+f"(c[0]), "+f"(c[1]), "+f"(c[2]), "+f"(c[3])
                 : "r"(a[0]), "r"(a[1]), "r"(a[2]), "r"(a[3]),
                   "r"(b[0]), "r"(b[1]));
}
__device__ __forceinline__ uint32_t pack_hi_h(float a, float b, float& ra, float& rb) {
    __half h0 = __float2half(a);
    __half h1 = __float2half(b);
    ra = a - __half2float(h0);
    rb = b - __half2float(h1);
    __half2 t = __halves2half2(h0, h1);
    return *(uint32_t*)&t;
}
__device__ __forceinline__ uint32_t pack_h(float a, float b) {
    __half2 t = __halves2half2(__float2half(a), __float2half(b));
    return *(uint32_t*)&t;
}
__device__ __forceinline__ void store_hl(__half* hi, __half* lo,
                                         size_t idx, float v0, float v1) {
    __half h0 = __float2half(v0);
    __half h1 = __float2half(v1);
    *(__half2*)(hi + idx) = __halves2half2(h0, h1);
    *(__half2*)(lo + idx) = __halves2half2(
        __float2half(v0 - __half2float(h0)),
        __float2half(v1 - __half2float(h1)));
}

// ---------------- split fp32 -> (hi, lo) fp16 ----------------
__global__ void split_kernel(const float* __restrict__ in,
                             __half* __restrict__ hi,
                             __half* __restrict__ lo, int n4)
{
    int i = blockIdx.x * blockDim.x + threadIdx.x;
    if (i >= n4) return;
    float4 v = ((const float4*)in)[i];
    float r0, r1, r2, r3;
    uint32_t h01 = pack_hi_h(v.x, v.y, r0, r1);
    uint32_t h23 = pack_hi_h(v.z, v.w, r2, r3);
    ((uint32_t*)hi)[2*i+0] = h01;
    ((uint32_t*)hi)[2*i+1] = h23;
    ((uint32_t*)lo)[2*i+0] = pack_h(r0, r1);
    ((uint32_t*)lo)[2*i+1] = pack_h(r2, r3);
}

// fused weight convert: hi only
__global__ void conv_w_kernel(const float* __restrict__ W0,
                              const float* __restrict__ W1,
                              const float* __restrict__ W2,
                              const float* __restrict__ W3,
                              __half* __restrict__ hi, int n4)
{
    const int z = blockIdx.z;
    const float* in = (z == 0) ? W0 : (z == 1) ? W1 : (z == 2) ? W2 : W3;
    hi += (size_t)z * D_MODEL * D_MODEL;
    int i = blockIdx.x * blockDim.x + threadIdx.x;
    if (i >= n4) return;
    float4 v = ((const float4*)in)[i];
    ((uint32_t*)hi)[2*i+0] = pack_h(v.x, v.y);
    ((uint32_t*)hi)[2*i+1] = pack_h(v.z, v.w);
}

// ---- mma.sync fp16 GEMM: 128x128, 256 thr, 8 warps 4m x 2n (warp 32x64),
//      BK=64, 2-stage depth-1 prefetch, 2 CTAs/SM.
//      two_term=1: C = (Ahi+Alo)*B ; two_term=0: C = Ahi*B (pure fp16). -----
#define BM 128
#define BN 128
#define BK 64
#define SROWB 144                     // 128 B data + 16 pad
#define TILE_B (128 * SROWB)          // 18432
#define AHI_OFF  0
#define ALO_OFF  (TILE_B)
#define BHI_OFF  (2*TILE_B)
#define STAGE_B  (3*TILE_B)           // 55296
#define GEMM_SMEM (2*STAGE_B)         // 110592 -> 2 CTAs/SM (221184 <= 228KB)
#define GTHREADS 256
#define WSZ ((size_t)D_MODEL*D_MODEL)

__global__ __launch_bounds__(GTHREADS, 2)
void gemm_mma_kernel(const __half* __restrict__ Ahi,
                     const __half* __restrict__ Alo,
                     const __half* __restrict__ Wh,
                     float* __restrict__ Cf,
                     __half* __restrict__ Qhi, __half* __restrict__ Qlo,
                     __half* __restrict__ Khi, __half* __restrict__ Vhi,
                     int qkv, int two_term)
{
    extern __shared__ char smem[];
    const uint32_t sbase = smem_u32(smem);
    const int tid = threadIdx.x;
    const int wid = tid >> 5;
    const int lane = tid & 31;
    const int wm = wid & 3;           // 4 m groups of 32
    const int wn = wid >> 2;          // 2 n groups of 64

    const int z = qkv ? blockIdx.z : 0;
    const int m0 = blockIdx.y * BM;
    const int n0 = blockIdx.x * BN;

    const __half* Ah = Ahi + (size_t)m0 * 1024;
    const __half* Al = Alo + (size_t)m0 * 1024;
    const __half* Bh = Wh + (qkv ? (size_t)z * WSZ : 0) + (size_t)n0 * 1024;
    const __half* srcs[3] = {Ah, Al, Bh};

    auto load_stage = [&](int ch, int st) {
        const int k0 = ch * BK;
        const uint32_t sb = sbase + st * STAGE_B;
#pragma unroll
        for (int i = 0; i < 12; i++) {
            const int idx = tid + i * GTHREADS;   // 0..3071
            const int t3 = idx >> 10;             // tile 0..2 (1024 xfers each)
            const int r = (idx >> 3) & 127;
            const int c = idx & 7;                // 8 x 16B = 128 B per row
            // skip the Alo tile when single-term (saves gmem+smem traffic)
            if (t3 == 1 && !two_term) continue;
            cp16(sb + t3 * TILE_B + (uint32_t)(r * SROWB + c * 16),
                 srcs[t3] + (size_t)r * 1024 + k0 + c * 8);
        }
        cp_commit();
    };

    float acc[2][8][4];
#pragma unroll
    for (int i = 0; i < 2; i++)
#pragma unroll
        for (int j = 0; j < 8; j++)
#pragma unroll
            for (int t = 0; t < 4; t++) acc[i][j][t] = 0.f;

    const int NCH = 1024 / BK;        // 16
    load_stage(0, 0);

    for (int ch = 0; ch < NCH; ch++) {
        asm volatile("cp.async.wait_group 0;");
        __syncthreads();              // chunk ch visible; other stage free
        if (ch + 1 < NCH) load_stage(ch + 1, (ch + 1) & 1);

        const uint32_t sb = sbase + (ch & 1) * STAGE_B;
#pragma unroll
        for (int ks = 0; ks < 4; ks++) {
            const int k16 = ks * 16;
            // B fragments resident for this k16 (8 n8 frags, hi only)
            uint32_t bhi[8][2];
#pragma unroll
            for (int nf16 = 0; nf16 < 4; nf16++) {
                const int nrow = wn * 64 + nf16 * 16 + ((lane >> 4) << 3) + (lane & 7);
                const int kc   = k16 + (((lane >> 3) & 1) << 3);
                const uint32_t off = (uint32_t)(nrow * SROWB + kc * 2);
                ldmatrix4(bhi[nf16*2][0], bhi[nf16*2][1],
                          bhi[nf16*2+1][0], bhi[nf16*2+1][1], sb + BHI_OFF + off);
            }
            // A fragments transient per mf
#pragma unroll
            for (int mf = 0; mf < 2; mf++) {
                uint32_t ahi[4], alo[4];
                const int row = wm * 32 + mf * 16 + (lane & 15);
                const int kc  = k16 + ((lane >> 4) << 3);
                const uint32_t off = (uint32_t)(row * SROWB + kc * 2);
                ldmatrix4(ahi[0], ahi[1], ahi[2], ahi[3], sb + AHI_OFF + off);
                if (two_term)
                    ldmatrix4(alo[0], alo[1], alo[2], alo[3], sb + ALO_OFF + off);
#pragma unroll
                for (int nf = 0; nf < 8; nf++) {
                    mma_f16(acc[mf][nf], ahi, bhi[nf]);
                    if (two_term) mma_f16(acc[mf][nf], alo, bhi[nf]);
                }
            }
        }
    }

    // ---- epilogue ----
    // Q pre-scaled by (1/8)*log2(e) for log2-domain softmax
    const float scale = qkv ? (z == 0 ? 0.1803368801111137f : 1.0f) : 1.0f;
    const int mode = qkv ? (z == 0 ? 1 : (z == 1 ? 2 : 3)) : 0;

#pragma unroll
    for (int mf = 0; mf < 2; mf++) {
#pragma unroll
        for (int nf = 0; nf < 8; nf++) {
            const int m_base = m0 + wm * 32 + mf * 16;
            const int n = n0 + wn * 64 + nf * 8 + (lane & 3) * 2;
            const int r0 = m_base + (lane >> 2);
            const int r1 = r0 + 8;
            const float v0 = acc[mf][nf][0] * scale;
            const float v1 = acc[mf][nf][1] * scale;
            const float v2 = acc[mf][nf][2] * scale;
            const float v3 = acc[mf][nf][3] * scale;
            if (mode == 0) {
                *(float2*)(Cf + (size_t)r0 * 1024 + n) = make_float2(v0, v1);
                *(float2*)(Cf + (size_t)r1 * 1024 + n) = make_float2(v2, v3);
            } else if (mode == 1) {          // Q: hi+lo, [bh][s][d]
                const int h = n >> 6, d = n & 63;
                const int bh0 = ((r0 >> 11) * HEADS) + h;
                const int bh1 = ((r1 >> 11) * HEADS) + h;
                store_hl(Qhi, Qlo, ((size_t)bh0 * SEQ + (r0 & 2047)) * DK + d, v0, v1);
                store_hl(Qhi, Qlo, ((size_t)bh1 * SEQ + (r1 & 2047)) * DK + d, v2, v3);
            } else if (mode == 2) {          // K: hi only, [bh][s][d]
                const int h = n >> 6, d = n & 63;
                const int bh0 = ((r0 >> 11) * HEADS) + h;
                const int bh1 = ((r1 >> 11) * HEADS) + h;
                *(__half2*)(Khi + ((size_t)bh0 * SEQ + (r0 & 2047)) * DK + d) =
                    __halves2half2(__float2half(v0), __float2half(v1));
                *(__half2*)(Khi + ((size_t)bh1 * SEQ + (r1 & 2047)) * DK + d) =
                    __halves2half2(__float2half(v2), __float2half(v3));
            } else {                         // V: hi only, transposed [bh][d][s]
                const int h = n >> 6, d = n & 63;
                const int bh0 = ((r0 >> 11) * HEADS) + h;
                const int bh1 = ((r1 >> 11) * HEADS) + h;
                const int s0 = r0 & 2047, s1 = r1 & 2047;
                Vhi[((size_t)bh0 * DK + d) * SEQ + s0] = __float2half(v0);
                Vhi[((size_t)bh0 * DK + d + 1) * SEQ + s0] = __float2half(v1);
                Vhi[((size_t)bh1 * DK + d) * SEQ + s1] = __float2half(v2);
                Vhi[((size_t)bh1 * DK + d + 1) * SEQ + s1] = __float2half(v3);
            }
        }
    }
}

// ---------------- mma.sync flash attention (causal, 2-term fp16) ------------
// 2 CTAs/SM; Q hi+lo in smem (re-read per block), K/V hi only.
// Scores in log2 domain -> exp2f softmax. Output: fp16 hi only.
#define ASTR 144
#define AQHI 0
#define AQLO 18432
#define ASTG0 36864
#define AKHI 0
#define AVHI 9216
#define ASTAGE_B 18432
#define ATT_SMEM (36864 + 2*18432)    // 73728

__global__ __launch_bounds__(256, 2)
void attn_mma_kernel(const __half* __restrict__ Qhi,
                     const __half* __restrict__ Qlo,
                     const __half* __restrict__ Khi,
                     const __half* __restrict__ Vhi,
                     __half* __restrict__ Ohi)
{
    extern __shared__ char smem[];
    const uint32_t sbase = smem_u32(smem);
    const int tid = threadIdx.x;
    const int w = tid >> 5;
    const int lane = tid & 31;
    const int qt = (int)gridDim.x - 1 - (int)blockIdx.x;  // big tiles first
    const int bh = blockIdx.y;

    const __half* Qh = Qhi + (size_t)bh * SEQ * DK + (size_t)qt * 128 * DK;
    const __half* Ql = Qlo + (size_t)bh * SEQ * DK + (size_t)qt * 128 * DK;
    const __half* Kh = Khi + (size_t)bh * SEQ * DK;
    const __half* Vh = Vhi + (size_t)bh * DK * SEQ;

    {
#pragma unroll
        for (int i = 0; i < 4; i++) {
            const int idx = tid + i * 256;
            const int row = idx >> 3, c = idx & 7;
            const uint32_t so = (uint32_t)(row * ASTR + c * 16);
            const size_t go = (size_t)row * DK + c * 8;
            cp16(sbase + AQHI + so, Qh + go);
            cp16(sbase + AQLO + so, Ql + go);
        }
        cp_commit();
    }

    const int jmax = 2 * qt + 1;
    auto load_kv = [&](int j, int st) {
        const uint32_t sb = sbase + ASTG0 + st * ASTAGE_B;
#pragma unroll
        for (int i = 0; i < 2; i++) {
            const int idx = tid + i * 256;
            const int row = idx >> 3, c = idx & 7;
            const uint32_t so = (uint32_t)(row * ASTR + c * 16);
            const size_t gk = (size_t)(j * 64 + row) * DK + c * 8;
            const size_t gv = (size_t)row * SEQ + j * 64 + c * 8;
            cp16(sb + AKHI + so, Kh + gk);
            cp16(sb + AVHI + so, Vh + gv);
        }
        cp_commit();
    };

    load_kv(0, 0);
    asm volatile("cp.async.wait_group 1;");
    __syncthreads();

    float o[8][4];
#pragma unroll
    for (int nf = 0; nf < 8; nf++)
#pragma unroll
        for (int t = 0; t < 4; t++) o[nf][t] = 0.f;
    float mA = -1e30f, mB = -1e30f, lA = 0.f, lB = 0.f;

    const int rowA_g = qt * 128 + w * 16 + (lane >> 2);
    const int rowB_g = rowA_g + 8;

    for (int j = 0; j <= jmax; j++) {
        if (j < jmax) load_kv(j + 1, (j + 1) & 1);
        if (j < jmax) asm volatile("cp.async.wait_group 1;");
        else          asm volatile("cp.async.wait_group 0;");
        __syncthreads();

        const uint32_t sb = sbase + ASTG0 + (j & 1) * ASTAGE_B;

        float s[8][4];
#pragma unroll
        for (int nf = 0; nf < 8; nf++)
#pragma unroll
            for (int t = 0; t < 4; t++) s[nf][t] = 0.f;
#pragma unroll
        for (int kb = 0; kb < 4; kb++) {
            uint32_t qh[4], ql[4];
            {
                const int row = w * 16 + (lane & 15);
                const int kc = kb * 16 + ((lane >> 4) << 3);
                const uint32_t off = (uint32_t)(row * ASTR + kc * 2);
                ldmatrix4(qh[0], qh[1], qh[2], qh[3], sbase + AQHI + off);
                ldmatrix4(ql[0], ql[1], ql[2], ql[3], sbase + AQLO + off);
            }
            uint32_t kh[8][2];
            const uint32_t kcoff = (uint32_t)((kb * 16 + (((lane >> 3) & 1) << 3)) * 2);
            const int nr = ((lane >> 4) << 3) + (lane & 7);
#pragma unroll
            for (int ng = 0; ng < 4; ng++) {
                const uint32_t off = (uint32_t)((ng * 16 + nr) * ASTR) + kcoff;
                ldmatrix4(kh[2*ng][0], kh[2*ng][1], kh[2*ng+1][0], kh[2*ng+1][1],
                          sb + AKHI + off);
            }
#pragma unroll
            for (int nf = 0; nf < 8; nf++) {
                mma_f16(s[nf], qh, kh[nf]);
                mma_f16(s[nf], ql, kh[nf]);
            }
        }

        if (j >= 2 * qt) {
#pragma unroll
            for (int nf = 0; nf < 8; nf++) {
                const int c0 = j * 64 + nf * 8 + (lane & 3) * 2;
                if (c0 > rowA_g)     s[nf][0] = -1e30f;
                if (c0 + 1 > rowA_g) s[nf][1] = -1e30f;
                if (c0 > rowB_g)     s[nf][2] = -1e30f;
                if (c0 + 1 > rowB_g) s[nf][3] = -1e30f;
            }
        }

        float bmA = -1e30f, bmB = -1e30f;
#pragma unroll
        for (int nf = 0; nf < 8; nf++) {
            bmA = fmaxf(bmA, fmaxf(s[nf][0], s[nf][1]));
            bmB = fmaxf(bmB, fmaxf(s[nf][2], s[nf][3]));
        }
        bmA = fmaxf(bmA, __shfl_xor_sync(0xffffffffu, bmA, 1));
        bmA = fmaxf(bmA, __shfl_xor_sync(0xffffffffu, bmA, 2));
        bmB = fmaxf(bmB, __shfl_xor_sync(0xffffffffu, bmB, 1));
        bmB = fmaxf(bmB, __shfl_xor_sync(0xffffffffu, bmB, 2));
        const float mnA = fmaxf(mA, bmA);
        const float mnB = fmaxf(mB, bmB);
        const float alA = exp2f(mA - mnA);
        const float alB = exp2f(mB - mnB);
        mA = mnA; mB = mnB;

        float sumA = 0.f, sumB = 0.f;
#pragma unroll
        for (int nf = 0; nf < 8; nf++) {
            s[nf][0] = exp2f(s[nf][0] - mnA);
            s[nf][1] = exp2f(s[nf][1] - mnA);
            s[nf][2] = exp2f(s[nf][2] - mnB);
            s[nf][3] = exp2f(s[nf][3] - mnB);
            sumA += s[nf][0] + s[nf][1];
            sumB += s[nf][2] + s[nf][3];
        }
        sumA += __shfl_xor_sync(0xffffffffu, sumA, 1);
        sumA += __shfl_xor_sync(0xffffffffu, sumA, 2);
        sumB += __shfl_xor_sync(0xffffffffu, sumB, 1);
        sumB += __shfl_xor_sync(0xffffffffu, sumB, 2);
        lA = lA * alA + sumA;
        lB = lB * alB + sumB;

#pragma unroll
        for (int nf = 0; nf < 8; nf++) {
            o[nf][0] *= alA; o[nf][1] *= alA;
            o[nf][2] *= alB; o[nf][3] *= alB;
        }

        // P fragments: fp16 hi + residual lo (A-side correction for PV)
        uint32_t pf_hi[4][4], pf_lo[4][4];
#pragma unroll
        for (int t = 0; t < 4; t++) {
            float r0, r1;
            pf_hi[t][0] = pack_hi_h(s[2*t][0],   s[2*t][1],   r0, r1); pf_lo[t][0] = pack_h(r0, r1);
            pf_hi[t][1] = pack_hi_h(s[2*t][2],   s[2*t][3],   r0, r1); pf_lo[t][1] = pack_h(r0, r1);
            pf_hi[t][2] = pack_hi_h(s[2*t+1][0], s[2*t+1][1], r0, r1); pf_lo[t][2] = pack_h(r0, r1);
            pf_hi[t][3] = pack_hi_h(s[2*t+1][2], s[2*t+1][3], r0, r1); pf_lo[t][3] = pack_h(r0, r1);
        }

#pragma unroll
        for (int t = 0; t < 4; t++) {
            uint32_t vh[8][2];
            const uint32_t kcoff = (uint32_t)((t * 16 + (((lane >> 3) & 1) << 3)) * 2);
            const int nr = ((lane >> 4) << 3) + (lane & 7);
#pragma unroll
            for (int ng = 0; ng < 4; ng++) {
                const uint32_t off = (uint32_t)((ng * 16 + nr) * ASTR) + kcoff;
                ldmatrix4(vh[2*ng][0], vh[2*ng][1], vh[2*ng+1][0], vh[2*ng+1][1],
                          sb + AVHI + off);
            }
#pragma unroll
            for (int nf = 0; nf < 8; nf++) {
                mma_f16(o[nf], pf_hi[t], vh[nf]);
                mma_f16(o[nf], pf_lo[t], vh[nf]);
            }
        }
        __syncthreads();
    }

    const float invA = 1.f / lA;
    const float invB = 1.f / lB;
    const int b = bh >> 4, h = bh & 15;
    const size_t mAi = (size_t)(b * SEQ) + (size_t)(rowA_g & 2047);
    const size_t mBi = mAi + 8;
#pragma unroll
    for (int nf = 0; nf < 8; nf++) {
        const int col = h * 64 + nf * 8 + (lane & 3) * 2;
        *(__half2*)(Ohi + mAi * D_MODEL + col) =
            __halves2half2(__float2half(o[nf][0] * invA), __float2half(o[nf][1] * invA));
        *(__half2*)(Ohi + mBi * D_MODEL + col) =
            __halves2half2(__float2half(o[nf][2] * invB), __float2half(o[nf][3] * invB));
    }
}

// ---------------------------------------------------------------------------
extern "C" void kernel_launch(void* const* d_in, const int* in_sizes, int n_in,
                              void* d_out, int out_size)
{
    (void)in_sizes; (void)n_in; (void)out_size;
    const float* x  = (const float*)d_in[0];
    const float* Wq = (const float*)d_in[1];
    const float* Wk = (const float*)d_in[2];
    const float* Wv = (const float*)d_in[3];
    const float* Wo = (const float*)d_in[4];
    float* out = (float*)d_out;

    __half *xhi, *xlo, *whi;
    __half *qhi, *qlo, *khi, *vhi, *ahi;
    cudaGetSymbolAddress((void**)&xhi, g_xhi);
    cudaGetSymbolAddress((void**)&xlo, g_xlo);
    cudaGetSymbolAddress((void**)&whi, g_whi);
    cudaGetSymbolAddress((void**)&qhi, g_qhi);
    cudaGetSymbolAddress((void**)&qlo, g_qlo);
    cudaGetSymbolAddress((void**)&khi, g_khi);
    cudaGetSymbolAddress((void**)&vhi, g_vhi);
    cudaGetSymbolAddress((void**)&ahi, g_ahi);

    cudaFuncSetAttribute(gemm_mma_kernel,
                         cudaFuncAttributeMaxDynamicSharedMemorySize, GEMM_SMEM);
    cudaFuncSetAttribute(attn_mma_kernel,
                         cudaFuncAttributeMaxDynamicSharedMemorySize, ATT_SMEM);

    const int WN4 = D_MODEL * D_MODEL / 4;
    const int XN4 = MTOT * D_MODEL / 4;

    split_kernel<<<XN4 / 256, 256>>>(x, xhi, xlo, XN4);
    conv_w_kernel<<<dim3(WN4 / 256, 1, 4), 256>>>(Wq, Wk, Wv, Wo, whi, WN4);

    // fused Q/K/V projections (blockIdx.z selects weight & output); 2-term
    dim3 gq(D_MODEL / BN, MTOT / BM, 3);     // (8, 64, 3)
    gemm_mma_kernel<<<gq, GTHREADS, GEMM_SMEM>>>(xhi, xlo, whi,
                                            nullptr, qhi, qlo, khi, vhi, 1, 1);

    attn_mma_kernel<<<dim3(SEQ / 128, BH), 256, ATT_SMEM>>>(qhi, qlo, khi, vhi, ahi);

    // output projection: pure fp16 (1-term)
    dim3 go(D_MODEL / BN, MTOT / BM, 1);     // (8, 64)
    gemm_mma_kernel<<<go, GTHREADS, GEMM_SMEM>>>(ahi, ahi, whi + 3*WSZ,
                                            out, qhi, qlo, khi, vhi, 0, 0);
}

// round 17
// speedup vs baseline: 1.7128x; 1.0969x over previous
#include <cuda_runtime.h>
#include <cuda_fp16.h>
#include <cstdint>

#define D_MODEL 1024
#define HEADS   16
#define DK      64
#define SEQ     2048
#define BATCH   4
#define BH      (BATCH*HEADS)
#define MTOT    (BATCH*SEQ)          // 8192

// ---------------- scratch (device globals: allocation-free) ----------------
__device__ __half g_xhi[MTOT*D_MODEL];
__device__ __half g_xlo[MTOT*D_MODEL];
__device__ __half g_whi[4][D_MODEL*D_MODEL];
__device__ __half g_qhi[BH*SEQ*DK];
__device__ __half g_qlo[BH*SEQ*DK];
__device__ __half g_khi[BH*SEQ*DK];
__device__ __half g_vhi[BH*DK*SEQ];   // transposed [bh][d][s]
__device__ __half g_ahi[MTOT*D_MODEL];

// ---------------- helpers ----------------
__device__ __forceinline__ uint32_t smem_u32(const void* p) {
    uint32_t a;
    asm("{ .reg .u64 t; cvta.to.shared.u64 t, %1; cvt.u32.u64 %0, t; }"
        : "=r"(a) : "l"(p));
    return a;
}
__device__ __forceinline__ void cp16(uint32_t saddr, const void* gaddr) {
    asm volatile("cp.async.cg.shared.global [%0], [%1], 16;"
                 :: "r"(saddr), "l"(gaddr));
}
__device__ __forceinline__ void cp_commit() {
    asm volatile("cp.async.commit_group;");
}
__device__ __forceinline__ void ldmatrix4(uint32_t& r0, uint32_t& r1,
                                          uint32_t& r2, uint32_t& r3, uint32_t addr) {
    asm volatile("ldmatrix.sync.aligned.m8n8.x4.shared.b16 {%0,%1,%2,%3}, [%4];"
                 : "=r"(r0), "=r"(r1), "=r"(r2), "=r"(r3) : "r"(addr));
}
__device__ __forceinline__ void mma_f16(float* c, const uint32_t* a, const uint32_t* b) {
    asm volatile("mma.sync.aligned.m16n8k16.row.col.f32.f16.f16.f32 "
                 "{%0,%1,%2,%3}, {%4,%5,%6,%7}, {%8,%9}, {%0,%1,%2,%3};"
                 : "+f"(c[0]), "+f"(c[1]), "+f"(c[2]), "+f"(c[3])
                 : "r"(a[0]), "r"(a[1]), "r"(a[2]), "r"(a[3]),
                   "r"(b[0]), "r"(b[1]));
}
__device__ __forceinline__ uint32_t pack_hi_h(float a, float b, float& ra, float& rb) {
    __half h0 = __float2half(a);
    __half h1 = __float2half(b);
    ra = a - __half2float(h0);
    rb = b - __half2float(h1);
    __half2 t = __halves2half2(h0, h1);
    return *(uint32_t*)&t;
}
__device__ __forceinline__ uint32_t pack_h(float a, float b) {
    __half2 t = __halves2half2(__float2half(a), __float2half(b));
    return *(uint32_t*)&t;
}
__device__ __forceinline__ void store_hl(__half* hi, __half* lo,
                                         size_t idx, float v0, float v1) {
    __half h0 = __float2half(v0);
    __half h1 = __float2half(v1);
    *(__half2*)(hi + idx) = __halves2half2(h0, h1);
    *(__half2*)(lo + idx) = __halves2half2(
        __float2half(v0 - __half2float(h0)),
        __float2half(v1 - __half2float(h1)));
}

// ---------------- split fp32 -> (hi, lo) fp16 ----------------
__global__ void split_kernel(const float* __restrict__ in,
                             __half* __restrict__ hi,
                             __half* __restrict__ lo, int n4)
{
    int i = blockIdx.x * blockDim.x + threadIdx.x;
    if (i >= n4) return;
    float4 v = ((const float4*)in)[i];
    float r0, r1, r2, r3;
    uint32_t h01 = pack_hi_h(v.x, v.y, r0, r1);
    uint32_t h23 = pack_hi_h(v.z, v.w, r2, r3);
    ((uint32_t*)hi)[2*i+0] = h01;
    ((uint32_t*)hi)[2*i+1] = h23;
    ((uint32_t*)lo)[2*i+0] = pack_h(r0, r1);
    ((uint32_t*)lo)[2*i+1] = pack_h(r2, r3);
}

// fused weight convert: hi only
__global__ void conv_w_kernel(const float* __restrict__ W0,
                              const float* __restrict__ W1,
                              const float* __restrict__ W2,
                              const float* __restrict__ W3,
                              __half* __restrict__ hi, int n4)
{
    const int z = blockIdx.z;
    const float* in = (z == 0) ? W0 : (z == 1) ? W1 : (z == 2) ? W2 : W3;
    hi += (size_t)z * D_MODEL * D_MODEL;
    int i = blockIdx.x * blockDim.x + threadIdx.x;
    if (i >= n4) return;
    float4 v = ((const float4*)in)[i];
    ((uint32_t*)hi)[2*i+0] = pack_h(v.x, v.y);
    ((uint32_t*)hi)[2*i+1] = pack_h(v.z, v.w);
}

// ---- mma.sync fp16 GEMM: 128x128, 256 thr, 8 warps 4m x 2n (warp 32x64),
//      BK=64, 2-stage depth-1 prefetch, 2 CTAs/SM.
//      two_term=1: C = (Ahi+Alo)*B ; two_term=0: C = Ahi*B (pure fp16). -----
#define BM 128
#define BN 128
#define BK 64
#define SROWB 144                     // 128 B data + 16 pad
#define TILE_B (128 * SROWB)          // 18432
#define AHI_OFF  0
#define ALO_OFF  (TILE_B)
#define BHI_OFF  (2*TILE_B)
#define STAGE_B  (3*TILE_B)           // 55296
#define GEMM_SMEM (2*STAGE_B)         // 110592 -> 2 CTAs/SM
#define GTHREADS 256
#define WSZ ((size_t)D_MODEL*D_MODEL)

__global__ __launch_bounds__(GTHREADS, 2)
void gemm_mma_kernel(const __half* __restrict__ Ahi,
                     const __half* __restrict__ Alo,
                     const __half* __restrict__ Wh,
                     float* __restrict__ Cf,
                     __half* __restrict__ Qhi, __half* __restrict__ Qlo,
                     __half* __restrict__ Khi, __half* __restrict__ Vhi,
                     int qkv, int two_term)
{
    extern __shared__ char smem[];
    const uint32_t sbase = smem_u32(smem);
    const int tid = threadIdx.x;
    const int wid = tid >> 5;
    const int lane = tid & 31;
    const int wm = wid & 3;           // 4 m groups of 32
    const int wn = wid >> 2;          // 2 n groups of 64

    const int z = qkv ? blockIdx.z : 0;
    const int m0 = blockIdx.y * BM;
    const int n0 = blockIdx.x * BN;

    const __half* Ah = Ahi + (size_t)m0 * 1024;
    const __half* Al = Alo + (size_t)m0 * 1024;
    const __half* Bh = Wh + (qkv ? (size_t)z * WSZ : 0) + (size_t)n0 * 1024;
    const __half* srcs[3] = {Ah, Al, Bh};

    auto load_stage = [&](int ch, int st) {
        const int k0 = ch * BK;
        const uint32_t sb = sbase + st * STAGE_B;
#pragma unroll
        for (int i = 0; i < 12; i++) {
            const int idx = tid + i * GTHREADS;   // 0..3071
            const int t3 = idx >> 10;             // tile 0..2 (1024 xfers each)
            const int r = (idx >> 3) & 127;
            const int c = idx & 7;                // 8 x 16B = 128 B per row
            if (t3 == 1 && !two_term) continue;
            cp16(sb + t3 * TILE_B + (uint32_t)(r * SROWB + c * 16),
                 srcs[t3] + (size_t)r * 1024 + k0 + c * 8);
        }
        cp_commit();
    };

    float acc[2][8][4];
#pragma unroll
    for (int i = 0; i < 2; i++)
#pragma unroll
        for (int j = 0; j < 8; j++)
#pragma unroll
            for (int t = 0; t < 4; t++) acc[i][j][t] = 0.f;

    const int NCH = 1024 / BK;        // 16
    load_stage(0, 0);

    for (int ch = 0; ch < NCH; ch++) {
        asm volatile("cp.async.wait_group 0;");
        __syncthreads();              // chunk ch visible; other stage free
        if (ch + 1 < NCH) load_stage(ch + 1, (ch + 1) & 1);

        const uint32_t sb = sbase + (ch & 1) * STAGE_B;
#pragma unroll
        for (int ks = 0; ks < 4; ks++) {
            const int k16 = ks * 16;
            uint32_t bhi[8][2];
#pragma unroll
            for (int nf16 = 0; nf16 < 4; nf16++) {
                const int nrow = wn * 64 + nf16 * 16 + ((lane >> 4) << 3) + (lane & 7);
                const int kc   = k16 + (((lane >> 3) & 1) << 3);
                const uint32_t off = (uint32_t)(nrow * SROWB + kc * 2);
                ldmatrix4(bhi[nf16*2][0], bhi[nf16*2][1],
                          bhi[nf16*2+1][0], bhi[nf16*2+1][1], sb + BHI_OFF + off);
            }
#pragma unroll
            for (int mf = 0; mf < 2; mf++) {
                uint32_t ahi[4], alo[4];
                const int row = wm * 32 + mf * 16 + (lane & 15);
                const int kc  = k16 + ((lane >> 4) << 3);
                const uint32_t off = (uint32_t)(row * SROWB + kc * 2);
                ldmatrix4(ahi[0], ahi[1], ahi[2], ahi[3], sb + AHI_OFF + off);
                if (two_term)
                    ldmatrix4(alo[0], alo[1], alo[2], alo[3], sb + ALO_OFF + off);
#pragma unroll
                for (int nf = 0; nf < 8; nf++) {
                    mma_f16(acc[mf][nf], ahi, bhi[nf]);
                    if (two_term) mma_f16(acc[mf][nf], alo, bhi[nf]);
                }
            }
        }
    }

    // ---- epilogue ----
    // Q pre-scaled by (1/8)*log2(e) for log2-domain softmax
    const float scale = qkv ? (z == 0 ? 0.1803368801111137f : 1.0f) : 1.0f;
    const int mode = qkv ? (z == 0 ? 1 : (z == 1 ? 2 : 3)) : 0;

#pragma unroll
    for (int mf = 0; mf < 2; mf++) {
#pragma unroll
        for (int nf = 0; nf < 8; nf++) {
            const int m_base = m0 + wm * 32 + mf * 16;
            const int n = n0 + wn * 64 + nf * 8 + (lane & 3) * 2;
            const int r0 = m_base + (lane >> 2);
            const int r1 = r0 + 8;
            const float v0 = acc[mf][nf][0] * scale;
            const float v1 = acc[mf][nf][1] * scale;
            const float v2 = acc[mf][nf][2] * scale;
            const float v3 = acc[mf][nf][3] * scale;
            if (mode == 0) {
                *(float2*)(Cf + (size_t)r0 * 1024 + n) = make_float2(v0, v1);
                *(float2*)(Cf + (size_t)r1 * 1024 + n) = make_float2(v2, v3);
            } else if (mode == 1) {          // Q: hi+lo, [bh][s][d]
                const int h = n >> 6, d = n & 63;
                const int bh0 = ((r0 >> 11) * HEADS) + h;
                const int bh1 = ((r1 >> 11) * HEADS) + h;
                store_hl(Qhi, Qlo, ((size_t)bh0 * SEQ + (r0 & 2047)) * DK + d, v0, v1);
                store_hl(Qhi, Qlo, ((size_t)bh1 * SEQ + (r1 & 2047)) * DK + d, v2, v3);
            } else if (mode == 2) {          // K: hi only, [bh][s][d]
                const int h = n >> 6, d = n & 63;
                const int bh0 = ((r0 >> 11) * HEADS) + h;
                const int bh1 = ((r1 >> 11) * HEADS) + h;
                *(__half2*)(Khi + ((size_t)bh0 * SEQ + (r0 & 2047)) * DK + d) =
                    __halves2half2(__float2half(v0), __float2half(v1));
                *(__half2*)(Khi + ((size_t)bh1 * SEQ + (r1 & 2047)) * DK + d) =
                    __halves2half2(__float2half(v2), __float2half(v3));
            } else {                         // V: hi only, transposed [bh][d][s]
                const int h = n >> 6, d = n & 63;
                const int bh0 = ((r0 >> 11) * HEADS) + h;
                const int bh1 = ((r1 >> 11) * HEADS) + h;
                const int s0 = r0 & 2047, s1 = r1 & 2047;
                Vhi[((size_t)bh0 * DK + d) * SEQ + s0] = __float2half(v0);
                Vhi[((size_t)bh0 * DK + d + 1) * SEQ + s0] = __float2half(v1);
                Vhi[((size_t)bh1 * DK + d) * SEQ + s1] = __float2half(v2);
                Vhi[((size_t)bh1 * DK + d + 1) * SEQ + s1] = __float2half(v3);
            }
        }
    }
}

// ---------------- mma.sync flash attention (causal, fp16) -------------------
// 2 CTAs/SM; QK^T 2-term (Q_hi resident, Q_lo re-read), PV 1-term (P hi only).
// Scores in log2 domain -> exp2f softmax. Output: fp16 hi only.
#define ASTR 144
#define AQHI 0
#define AQLO 18432
#define ASTG0 36864
#define AKHI 0
#define AVHI 9216
#define ASTAGE_B 18432
#define ATT_SMEM (36864 + 2*18432)    // 73728

__global__ __launch_bounds__(256, 2)
void attn_mma_kernel(const __half* __restrict__ Qhi,
                     const __half* __restrict__ Qlo,
                     const __half* __restrict__ Khi,
                     const __half* __restrict__ Vhi,
                     __half* __restrict__ Ohi)
{
    extern __shared__ char smem[];
    const uint32_t sbase = smem_u32(smem);
    const int tid = threadIdx.x;
    const int w = tid >> 5;
    const int lane = tid & 31;
    const int qt = (int)gridDim.x - 1 - (int)blockIdx.x;  // big tiles first
    const int bh = blockIdx.y;

    const __half* Qh = Qhi + (size_t)bh * SEQ * DK + (size_t)qt * 128 * DK;
    const __half* Ql = Qlo + (size_t)bh * SEQ * DK + (size_t)qt * 128 * DK;
    const __half* Kh = Khi + (size_t)bh * SEQ * DK;
    const __half* Vh = Vhi + (size_t)bh * DK * SEQ;

    {
#pragma unroll
        for (int i = 0; i < 4; i++) {
            const int idx = tid + i * 256;
            const int row = idx >> 3, c = idx & 7;
            const uint32_t so = (uint32_t)(row * ASTR + c * 16);
            const size_t go = (size_t)row * DK + c * 8;
            cp16(sbase + AQHI + so, Qh + go);
            cp16(sbase + AQLO + so, Ql + go);
        }
        cp_commit();
    }

    const int jmax = 2 * qt + 1;
    auto load_kv = [&](int j, int st) {
        const uint32_t sb = sbase + ASTG0 + st * ASTAGE_B;
#pragma unroll
        for (int i = 0; i < 2; i++) {
            const int idx = tid + i * 256;
            const int row = idx >> 3, c = idx & 7;
            const uint32_t so = (uint32_t)(row * ASTR + c * 16);
            const size_t gk = (size_t)(j * 64 + row) * DK + c * 8;
            const size_t gv = (size_t)row * SEQ + j * 64 + c * 8;
            cp16(sb + AKHI + so, Kh + gk);
            cp16(sb + AVHI + so, Vh + gv);
        }
        cp_commit();
    };

    load_kv(0, 0);
    asm volatile("cp.async.wait_group 1;");
    __syncthreads();

    // Q_hi fragments resident (16 regs); Q_lo re-read from smem per kb
    uint32_t qhf[4][4];
#pragma unroll
    for (int kb = 0; kb < 4; kb++) {
        const int row = w * 16 + (lane & 15);
        const int kc = kb * 16 + ((lane >> 4) << 3);
        const uint32_t off = (uint32_t)(row * ASTR + kc * 2);
        ldmatrix4(qhf[kb][0], qhf[kb][1], qhf[kb][2], qhf[kb][3], sbase + AQHI + off);
    }

    float o[8][4];
#pragma unroll
    for (int nf = 0; nf < 8; nf++)
#pragma unroll
        for (int t = 0; t < 4; t++) o[nf][t] = 0.f;
    float mA = -1e30f, mB = -1e30f, lA = 0.f, lB = 0.f;

    const int rowA_g = qt * 128 + w * 16 + (lane >> 2);
    const int rowB_g = rowA_g + 8;

    for (int j = 0; j <= jmax; j++) {
        if (j < jmax) load_kv(j + 1, (j + 1) & 1);
        if (j < jmax) asm volatile("cp.async.wait_group 1;");
        else          asm volatile("cp.async.wait_group 0;");
        __syncthreads();

        const uint32_t sb = sbase + ASTG0 + (j & 1) * ASTAGE_B;

        float s[8][4];
#pragma unroll
        for (int nf = 0; nf < 8; nf++)
#pragma unroll
            for (int t = 0; t < 4; t++) s[nf][t] = 0.f;
#pragma unroll
        for (int kb = 0; kb < 4; kb++) {
            uint32_t ql[4];
            {
                const int row = w * 16 + (lane & 15);
                const int kc = kb * 16 + ((lane >> 4) << 3);
                const uint32_t off = (uint32_t)(row * ASTR + kc * 2);
                ldmatrix4(ql[0], ql[1], ql[2], ql[3], sbase + AQLO + off);
            }
            uint32_t kh[8][2];
            const uint32_t kcoff = (uint32_t)((kb * 16 + (((lane >> 3) & 1) << 3)) * 2);
            const int nr = ((lane >> 4) << 3) + (lane & 7);
#pragma unroll
            for (int ng = 0; ng < 4; ng++) {
                const uint32_t off = (uint32_t)((ng * 16 + nr) * ASTR) + kcoff;
                ldmatrix4(kh[2*ng][0], kh[2*ng][1], kh[2*ng+1][0], kh[2*ng+1][1],
                          sb + AKHI + off);
            }
#pragma unroll
            for (int nf = 0; nf < 8; nf++) {
                mma_f16(s[nf], qhf[kb], kh[nf]);
                mma_f16(s[nf], ql, kh[nf]);
            }
        }

        if (j >= 2 * qt) {
#pragma unroll
            for (int nf = 0; nf < 8; nf++) {
                const int c0 = j * 64 + nf * 8 + (lane & 3) * 2;
                if (c0 > rowA_g)     s[nf][0] = -1e30f;
                if (c0 + 1 > rowA_g) s[nf][1] = -1e30f;
                if (c0 > rowB_g)     s[nf][2] = -1e30f;
                if (c0 + 1 > rowB_g) s[nf][3] = -1e30f;
            }
        }

        float bmA = -1e30f, bmB = -1e30f;
#pragma unroll
        for (int nf = 0; nf < 8; nf++) {
            bmA = fmaxf(bmA, fmaxf(s[nf][0], s[nf][1]));
            bmB = fmaxf(bmB, fmaxf(s[nf][2], s[nf][3]));
        }
        bmA = fmaxf(bmA, __shfl_xor_sync(0xffffffffu, bmA, 1));
        bmA = fmaxf(bmA, __shfl_xor_sync(0xffffffffu, bmA, 2));
        bmB = fmaxf(bmB, __shfl_xor_sync(0xffffffffu, bmB, 1));
        bmB = fmaxf(bmB, __shfl_xor_sync(0xffffffffu, bmB, 2));
        const float mnA = fmaxf(mA, bmA);
        const float mnB = fmaxf(mB, bmB);
        const float alA = exp2f(mA - mnA);
        const float alB = exp2f(mB - mnB);
        mA = mnA; mB = mnB;

        float sumA = 0.f, sumB = 0.f;
#pragma unroll
        for (int nf = 0; nf < 8; nf++) {
            s[nf][0] = exp2f(s[nf][0] - mnA);
            s[nf][1] = exp2f(s[nf][1] - mnA);
            s[nf][2] = exp2f(s[nf][2] - mnB);
            s[nf][3] = exp2f(s[nf][3] - mnB);
            sumA += s[nf][0] + s[nf][1];
            sumB += s[nf][2] + s[nf][3];
        }
        sumA += __shfl_xor_sync(0xffffffffu, sumA, 1);
        sumA += __shfl_xor_sync(0xffffffffu, sumA, 2);
        sumB += __shfl_xor_sync(0xffffffffu, sumB, 1);
        sumB += __shfl_xor_sync(0xffffffffu, sumB, 2);
        lA = lA * alA + sumA;
        lB = lB * alB + sumB;

#pragma unroll
        for (int nf = 0; nf < 8; nf++) {
            o[nf][0] *= alA; o[nf][1] *= alA;
            o[nf][2] *= alB; o[nf][3] *= alB;
        }

        // P fragments: fp16 hi only (PV 1-term)
        uint32_t pf[4][4];
#pragma unroll
        for (int t = 0; t < 4; t++) {
            pf[t][0] = pack_h(s[2*t][0],   s[2*t][1]);
            pf[t][1] = pack_h(s[2*t][2],   s[2*t][3]);
            pf[t][2] = pack_h(s[2*t+1][0], s[2*t+1][1]);
            pf[t][3] = pack_h(s[2*t+1][2], s[2*t+1][3]);
        }

#pragma unroll
        for (int t = 0; t < 4; t++) {
            uint32_t vh[8][2];
            const uint32_t kcoff = (uint32_t)((t * 16 + (((lane >> 3) & 1) << 3)) * 2);
            const int nr = ((lane >> 4) << 3) + (lane & 7);
#pragma unroll
            for (int ng = 0; ng < 4; ng++) {
                const uint32_t off = (uint32_t)((ng * 16 + nr) * ASTR) + kcoff;
                ldmatrix4(vh[2*ng][0], vh[2*ng][1], vh[2*ng+1][0], vh[2*ng+1][1],
                          sb + AVHI + off);
            }
#pragma unroll
            for (int nf = 0; nf < 8; nf++)
                mma_f16(o[nf], pf[t], vh[nf]);
        }
        __syncthreads();
    }

    const float invA = 1.f / lA;
    const float invB = 1.f / lB;
    const int b = bh >> 4, h = bh & 15;
    const size_t mAi = (size_t)(b * SEQ) + (size_t)(rowA_g & 2047);
    const size_t mBi = mAi + 8;
#pragma unroll
    for (int nf = 0; nf < 8; nf++) {
        const int col = h * 64 + nf * 8 + (lane & 3) * 2;
        *(__half2*)(Ohi + mAi * D_MODEL + col) =
            __halves2half2(__float2half(o[nf][0] * invA), __float2half(o[nf][1] * invA));
        *(__half2*)(Ohi + mBi * D_MODEL + col) =
            __halves2half2(__float2half(o[nf][2] * invB), __float2half(o[nf][3] * invB));
    }
}

// ---------------------------------------------------------------------------
extern "C" void kernel_launch(void* const* d_in, const int* in_sizes, int n_in,
                              void* d_out, int out_size)
{
    (void)in_sizes; (void)n_in; (void)out_size;
    const float* x  = (const float*)d_in[0];
    const float* Wq = (const float*)d_in[1];
    const float* Wk = (const float*)d_in[2];
    const float* Wv = (const float*)d_in[3];
    const float* Wo = (const float*)d_in[4];
    float* out = (float*)d_out;

    __half *xhi, *xlo, *whi;
    __half *qhi, *qlo, *khi, *vhi, *ahi;
    cudaGetSymbolAddress((void**)&xhi, g_xhi);
    cudaGetSymbolAddress((void**)&xlo, g_xlo);
    cudaGetSymbolAddress((void**)&whi, g_whi);
    cudaGetSymbolAddress((void**)&qhi, g_qhi);
    cudaGetSymbolAddress((void**)&qlo, g_qlo);
    cudaGetSymbolAddress((void**)&khi, g_khi);
    cudaGetSymbolAddress((void**)&vhi, g_vhi);
    cudaGetSymbolAddress((void**)&ahi, g_ahi);

    cudaFuncSetAttribute(gemm_mma_kernel,
                         cudaFuncAttributeMaxDynamicSharedMemorySize, GEMM_SMEM);
    cudaFuncSetAttribute(attn_mma_kernel,
                         cudaFuncAttributeMaxDynamicSharedMemorySize, ATT_SMEM);

    const int WN4 = D_MODEL * D_MODEL / 4;
    const int XN4 = MTOT * D_MODEL / 4;

    split_kernel<<<XN4 / 256, 256>>>(x, xhi, xlo, XN4);
    conv_w_kernel<<<dim3(WN4 / 256, 1, 4), 256>>>(Wq, Wk, Wv, Wo, whi, WN4);

    // fused Q/K/V projections (blockIdx.z selects weight & output); 2-term
    dim3 gq(D_MODEL / BN, MTOT / BM, 3);     // (8, 64, 3)
    gemm_mma_kernel<<<gq, GTHREADS, GEMM_SMEM>>>(xhi, xlo, whi,
                                            nullptr, qhi, qlo, khi, vhi, 1, 1);

    attn_mma_kernel<<<dim3(SEQ / 128, BH), 256, ATT_SMEM>>>(qhi, qlo, khi, vhi, ahi);

    // output projection: pure fp16 (1-term)
    dim3 go(D_MODEL / BN, MTOT / BM, 1);     // (8, 64)
    gemm_mma_kernel<<<go, GTHREADS, GEMM_SMEM>>>(ahi, ahi, whi + 3*WSZ,
                                            out, qhi, qlo, khi, vhi, 0, 0);
}